// round 10
// baseline (speedup 1.0000x reference)
#include <cuda_runtime.h>
#include <cstdint>
#include <math.h>

#define S_LEN 2048
#define D_DIM 2048
#define B_SZ  2
#define NH    16
#define NKV   4
#define HD    128
#define NTOK  (B_SZ * S_LEN)   /* 4096 */
#define KVD   (NKV * HD)       /* 512  */
#define EPS_F 1.1920929e-07f

// Scratch (allocation-free rule: __device__ globals)
__device__ float g_Q[(size_t)NTOK * D_DIM];    // tf32+perm after rms_rope
__device__ float g_K[(size_t)NTOK * KVD];
__device__ float g_Vt[(size_t)KVD * NTOK];     // V^T [KVD][NTOK], tok-perm
__device__ float g_AO[(size_t)NTOK * D_DIM];   // tf32+perm (written by flash)
// Pre-converted (tf32-rounded, 16-chunk k-permuted) operands
__device__ float g_xt[(size_t)NTOK * D_DIM];
__device__ float g_Wqt[(size_t)D_DIM * D_DIM];
__device__ float g_Wkt[(size_t)KVD * D_DIM];
__device__ float g_Wvt[(size_t)KVD * D_DIM];
__device__ float g_Wot[(size_t)D_DIM * D_DIM];

__device__ __forceinline__ uint32_t f2tf32(float x) {
    uint32_t r;
    asm("cvt.rna.tf32.f32 %0, %1;" : "=r"(r) : "f"(x));
    return r;
}
__device__ __forceinline__ uint32_t smem_u32(const void* p) {
    uint32_t a;
    asm("{ .reg .u64 t; cvta.to.shared.u64 t, %1; cvt.u32.u64 %0, t; }"
        : "=r"(a) : "l"(p));
    return a;
}
__device__ __forceinline__ int perm16(int c) {
    return (c & ~15) | ((c & 3) << 2) | ((c >> 2) & 3);
}

#define CP_ASYNC16(dst, src) \
    asm volatile("cp.async.cg.shared.global [%0], [%1], 16;" :: "r"(dst), "l"(src))
#define CP_COMMIT() asm volatile("cp.async.commit_group;" ::: "memory")
#define CP_WAIT(n)  asm volatile("cp.async.wait_group %0;" :: "n"(n) : "memory")

// mma.sync m16n8k8 tf32
__device__ __forceinline__ void mma_tf32(
    float& c0, float& c1, float& c2, float& c3,
    uint32_t a0, uint32_t a1, uint32_t a2, uint32_t a3,
    uint32_t b0, uint32_t b1)
{
    asm volatile(
        "mma.sync.aligned.m16n8k8.row.col.f32.tf32.tf32.f32 "
        "{%0,%1,%2,%3}, {%4,%5,%6,%7}, {%8,%9}, {%0,%1,%2,%3};"
        : "+f"(c0), "+f"(c1), "+f"(c2), "+f"(c3)
        : "r"(a0), "r"(a1), "r"(a2), "r"(a3), "r"(b0), "r"(b1));
}

// ---------------------------------------------------------------------------
// Segmented convert: fp32 -> tf32(rna) + 16-chunk k-perm, one launch.
// ---------------------------------------------------------------------------
#define N4_X  (NTOK * D_DIM / 4)
#define N4_WQ (D_DIM * D_DIM / 4)
#define N4_WK (KVD * D_DIM / 4)
#define SEG0 (N4_X)
#define SEG1 (SEG0 + N4_WQ)
#define SEG2 (SEG1 + N4_WK)
#define SEG3 (SEG2 + N4_WK)
#define SEG4 (SEG3 + N4_WQ)

__global__ __launch_bounds__(256) void convert_all(
    const float* __restrict__ x,  const float* __restrict__ Wq,
    const float* __restrict__ Wk, const float* __restrict__ Wv,
    const float* __restrict__ Wo)
{
    int i = blockIdx.x * 256 + threadIdx.x;
    if (i >= SEG4) return;
    const float* src;
    float* dst;
    int j;
    if (i < SEG0)      { src = x;  dst = g_xt;  j = i; }
    else if (i < SEG1) { src = Wq; dst = g_Wqt; j = i - SEG0; }
    else if (i < SEG2) { src = Wk; dst = g_Wkt; j = i - SEG1; }
    else if (i < SEG3) { src = Wv; dst = g_Wvt; j = i - SEG2; }
    else               { src = Wo; dst = g_Wot; j = i - SEG3; }
    float4 v = ((const float4*)src)[j];
    int f0 = j << 2;
    int base = f0 & ~15;
    int q = (f0 >> 2) & 3;
    dst[base + 0 + q]  = __uint_as_float(f2tf32(v.x));
    dst[base + 4 + q]  = __uint_as_float(f2tf32(v.y));
    dst[base + 8 + q]  = __uint_as_float(f2tf32(v.z));
    dst[base + 12 + q] = __uint_as_float(f2tf32(v.w));
}

// ---------------------------------------------------------------------------
// Shared GEMM body: 128x128 tile, 4-stage cp.async, BK=16.
// ---------------------------------------------------------------------------
struct GemmJob {
    const float* Ap;
    const float* Bp;
    const float* bias;
    float* C;
    int N, K, rowBase, colBase, vmode;
};

__device__ __forceinline__ void gemm_body(const GemmJob& jb, float* gsm)
{
    float* sA = gsm;
    float* sB = gsm + 4 * 2048;
    const uint32_t sAu = smem_u32(sA);
    const uint32_t sBu = smem_u32(sB);

    const int tid = threadIdx.x;
    const int lane = tid & 31, wid = tid >> 5;
    const int wm = wid >> 1, wn = wid & 1;
    const int g = lane >> 2, tg = lane & 3;
    const int lrow = tid >> 2;
    const int lc4 = tid & 3;
    const int K = jb.K;

    float acc[2][8][4];
#pragma unroll
    for (int mt = 0; mt < 2; mt++)
#pragma unroll
        for (int nt = 0; nt < 8; nt++)
#pragma unroll
            for (int r = 0; r < 4; r++) acc[mt][nt][r] = 0.0f;

    const int NT = K >> 4;

    auto issue = [&](int slot, int t) {
#pragma unroll
        for (int p = 0; p < 2; p++) {
            const int row = lrow + p * 64;
            const size_t go = (size_t)row * K + t * 16 + lc4 * 4;
            const uint32_t so = (uint32_t)((slot * 2048 + row * 16 + lc4 * 4) * 4);
            CP_ASYNC16(sAu + so, jb.Ap + go);
            CP_ASYNC16(sBu + so, jb.Bp + go);
        }
    };

#pragma unroll
    for (int s = 0; s < 3; s++) { issue(s, s); CP_COMMIT(); }

    for (int t = 0; t < NT; t++) {
        CP_WAIT(2);
        __syncthreads();
        const int tn = t + 3;
        if (tn < NT) issue(tn & 3, tn);
        CP_COMMIT();

        const float* bA = sA + (t & 3) * 2048;
        const float* bB = sB + (t & 3) * 2048;

        uint4 afr[2][2];
#pragma unroll
        for (int mt = 0; mt < 2; mt++) {
            const int r0 = wm * 32 + mt * 16 + g;
            afr[mt][0] = *(const uint4*)&bA[r0 * 16 + 4 * tg];
            afr[mt][1] = *(const uint4*)&bA[(r0 + 8) * 16 + 4 * tg];
        }
        uint4 bfr[8];
#pragma unroll
        for (int nt = 0; nt < 8; nt++)
            bfr[nt] = *(const uint4*)&bB[(wn * 64 + nt * 8 + g) * 16 + 4 * tg];

#pragma unroll
        for (int mt = 0; mt < 2; mt++)
#pragma unroll
            for (int nt = 0; nt < 8; nt++)
                mma_tf32(acc[mt][nt][0], acc[mt][nt][1], acc[mt][nt][2], acc[mt][nt][3],
                         afr[mt][0].x, afr[mt][1].x, afr[mt][0].y, afr[mt][1].y,
                         bfr[nt].x, bfr[nt].y);
#pragma unroll
        for (int mt = 0; mt < 2; mt++)
#pragma unroll
            for (int nt = 0; nt < 8; nt++)
                mma_tf32(acc[mt][nt][0], acc[mt][nt][1], acc[mt][nt][2], acc[mt][nt][3],
                         afr[mt][0].z, afr[mt][1].z, afr[mt][0].w, afr[mt][1].w,
                         bfr[nt].z, bfr[nt].w);
    }

    if (!jb.vmode) {
#pragma unroll
        for (int mt = 0; mt < 2; mt++) {
            const int row = jb.rowBase + wm * 32 + mt * 16 + g;
#pragma unroll
            for (int nt = 0; nt < 8; nt++) {
                const int col = jb.colBase + wn * 64 + nt * 8 + 2 * tg;
                const float2 bb = *(const float2*)(jb.bias + col);
                float2 o0, o1;
                o0.x = acc[mt][nt][0] + bb.x;
                o0.y = acc[mt][nt][1] + bb.y;
                o1.x = acc[mt][nt][2] + bb.x;
                o1.y = acc[mt][nt][3] + bb.y;
                *(float2*)(jb.C + (size_t)row * jb.N + col) = o0;
                *(float2*)(jb.C + (size_t)(row + 8) * jb.N + col) = o1;
            }
        }
    } else {
#pragma unroll
        for (int mt = 0; mt < 2; mt++) {
            const int r = jb.rowBase + wm * 32 + mt * 16 + g;
            const int rp0 = perm16(r);
            const int rp1 = perm16(r + 8);
#pragma unroll
            for (int nt = 0; nt < 8; nt++) {
                const int col = jb.colBase + wn * 64 + nt * 8 + 2 * tg;
                const float b0 = jb.bias[col], b1 = jb.bias[col + 1];
                jb.C[(size_t)col * NTOK + rp0] =
                    __uint_as_float(f2tf32(acc[mt][nt][0] + b0));
                jb.C[(size_t)(col + 1) * NTOK + rp0] =
                    __uint_as_float(f2tf32(acc[mt][nt][1] + b1));
                jb.C[(size_t)col * NTOK + rp1] =
                    __uint_as_float(f2tf32(acc[mt][nt][2] + b0));
                jb.C[(size_t)(col + 1) * NTOK + rp1] =
                    __uint_as_float(f2tf32(acc[mt][nt][3] + b1));
            }
        }
    }
}

// ---------------------------------------------------------------------------
// Fused Q+K+V projection, one launch, flat 768-block grid.
// ---------------------------------------------------------------------------
__global__ __launch_bounds__(256) void gemm_qkv(
    const float* __restrict__ bq, const float* __restrict__ bk,
    const float* __restrict__ bv)
{
    extern __shared__ __align__(16) float gsm[];
    GemmJob jb;
    jb.K = D_DIM;
    const int blk = blockIdx.x;
    if (blk < 512) {
        jb.rowBase = (blk >> 4) * 128; jb.colBase = (blk & 15) * 128;
        jb.Bp = g_Wqt + (size_t)jb.colBase * D_DIM;
        jb.bias = bq; jb.C = g_Q; jb.N = D_DIM; jb.vmode = 0;
    } else if (blk < 640) {
        const int t = blk - 512;
        jb.rowBase = (t >> 2) * 128; jb.colBase = (t & 3) * 128;
        jb.Bp = g_Wkt + (size_t)jb.colBase * D_DIM;
        jb.bias = bk; jb.C = g_K; jb.N = KVD; jb.vmode = 0;
    } else {
        const int t = blk - 640;
        jb.rowBase = (t >> 2) * 128; jb.colBase = (t & 3) * 128;
        jb.Bp = g_Wvt + (size_t)jb.colBase * D_DIM;
        jb.bias = bv; jb.C = g_Vt; jb.N = KVD; jb.vmode = 1;
    }
    jb.Ap = g_xt + (size_t)jb.rowBase * D_DIM;
    gemm_body(jb, gsm);
}

__global__ __launch_bounds__(256) void gemm_out(
    const float* __restrict__ bias, float* __restrict__ C)
{
    extern __shared__ __align__(16) float gsm[];
    GemmJob jb;
    jb.K = D_DIM;
    jb.rowBase = blockIdx.y * 128;
    jb.colBase = blockIdx.x * 128;
    jb.Ap = g_AO + (size_t)jb.rowBase * D_DIM;
    jb.Bp = g_Wot + (size_t)jb.colBase * D_DIM;
    jb.bias = bias; jb.C = C; jb.N = D_DIM; jb.vmode = 0;
    gemm_body(jb, gsm);
}

// ---------------------------------------------------------------------------
// Fused RMSNorm + RoPE for Q and K in one launch; writes tf32+perm in place.
// ---------------------------------------------------------------------------
#define RMS_QW (NTOK * NH)
#define RMS_TW (NTOK * (NH + NKV))

__global__ __launch_bounds__(256) void rms_rope_all(
    float* __restrict__ Q, float* __restrict__ K,
    const float* __restrict__ gain)
{
    int gw = (blockIdx.x * blockDim.x + threadIdx.x) >> 5;
    int lane = threadIdx.x & 31;
    if (gw >= RMS_TW) return;

    float* p;
    int token;
    float gmul;
    if (gw < RMS_QW) {
        token = gw >> 4;
        int h = gw & 15;
        p = Q + (size_t)token * D_DIM + h * HD;
        gmul = gain[h] * 0.088388347648318447f;
    } else {
        int gw2 = gw - RMS_QW;
        token = gw2 >> 2;
        int h = gw2 & 3;
        p = K + (size_t)token * KVD + h * HD;
        gmul = 1.0f;
    }

    float a1 = p[lane];
    float b1 = p[lane + 32];
    float a2 = p[lane + 64];
    float b2 = p[lane + 96];

    float ss = a1 * a1 + b1 * b1 + a2 * a2 + b2 * b2;
#pragma unroll
    for (int off = 16; off; off >>= 1)
        ss += __shfl_xor_sync(0xffffffffu, ss, off);

    float g = rsqrtf(ss * (1.0f / 128.0f) + EPS_F) * gmul;

    int pos = token & (S_LEN - 1);
    const float c = -0.20762050593046015f;  // -log2(10000)/64
    float invfa = exp2f(c * (float)lane);
    float invfb = exp2f(c * (float)(lane + 32));
    float sa, ca, sb, cb;
    sincosf((float)pos * invfa, &sa, &ca);
    sincosf((float)pos * invfb, &sb, &cb);

    p[perm16(lane)]      = __uint_as_float(f2tf32((a1 * ca + a2 * sa) * g));
    p[perm16(lane + 64)] = __uint_as_float(f2tf32((a2 * ca - a1 * sa) * g));
    p[perm16(lane + 32)] = __uint_as_float(f2tf32((b1 * cb + b2 * sb) * g));
    p[perm16(lane + 96)] = __uint_as_float(f2tf32((b2 * cb - b1 * sb) * g));
}

// ---------------------------------------------------------------------------
// Causal flash attention v4: q-tile 64, 256 threads (8 warps), 2 CTAs/SM.
// Warp pair p = w>>1 owns 16 q-rows; both compute full QK^T (Q streamed
// from L1), exp split by key-half, PV split by d-half. Named pair barrier.
// ---------------------------------------------------------------------------
#define QROWS 132
#define VROWS 68
#define PROWS 68
#define FL_SMEM ((64 * QROWS + 128 * VROWS + 64 * PROWS + 128) * 4)  /* 86528 */

__global__ __launch_bounds__(256, 2) void flash_tf32()
{
    extern __shared__ __align__(16) uint32_t usm[];
    uint32_t* Ks = usm;                    // [64][QROWS]
    uint32_t* Vt = Ks + 64 * QROWS;        // [128][VROWS]
    uint32_t* Ps = Vt + 128 * VROWS;       // [64][PROWS]
    float* Sp = (float*)(Ps + 64 * PROWS); // [4 pairs][2 halves][16] partial sums
    const uint32_t Ksu = smem_u32(Ks);
    const uint32_t Vtu = smem_u32(Vt);

    const int qt = gridDim.x - 1 - blockIdx.x;   // LPT
    const int bh = blockIdx.y;
    const int b = bh >> 4, h = bh & 15, kvh = h >> 2;
    const int tid = threadIdx.x;
    const int lane = tid & 31, w = tid >> 5;
    const int pr = w >> 1, half = w & 1;
    const int g = lane >> 2, tg = lane & 3;

    const float* Kg = g_K + ((size_t)b * S_LEN) * KVD + kvh * HD;
    const float* Vg = g_Vt + (size_t)(kvh * HD) * NTOK + b * S_LEN;

    // Loaders: 256 threads, 8 x cp.async(16B) each per tile.
    const int krow = tid >> 2, kq = tid & 3;     // K: [64][128]
    const int vd = tid >> 1, vh = tid & 1;       // Vt: [128][64]
    auto issueK = [&](int kt) {
        const float* src = Kg + (size_t)(kt * 64 + krow) * KVD + kq * 32;
        const uint32_t dst = Ksu + (uint32_t)((krow * QROWS + kq * 32) * 4);
#pragma unroll
        for (int i = 0; i < 8; i++)
            CP_ASYNC16(dst + i * 16, src + i * 4);
    };
    auto issueV = [&](int kt) {
        const float* src = Vg + (size_t)vd * NTOK + kt * 64 + vh * 32;
        const uint32_t dst = Vtu + (uint32_t)((vd * VROWS + vh * 32) * 4);
#pragma unroll
        for (int i = 0; i < 8; i++)
            CP_ASYNC16(dst + i * 16, src + i * 4);
    };

    const int nkt = qt + 1;
    issueK(0); CP_COMMIT();
    issueV(0); CP_COMMIT();

    // Q row pointers (tf32+permuted in gmem; streamed via L1 each tile)
    const float* Qr0 = g_Q +
        ((size_t)(b * S_LEN + qt * 64 + pr * 16 + g)) * D_DIM + h * HD + 4 * tg;
    const float* Qr1 = Qr0 + 8 * D_DIM;

    float o[8][4];
#pragma unroll
    for (int nt = 0; nt < 8; nt++)
#pragma unroll
        for (int r = 0; r < 4; r++) o[nt][r] = 0.0f;
    float m0 = -1e30f, m1 = -1e30f, l0 = 0.0f, l1 = 0.0f;

    for (int kt = 0; kt < nkt; kt++) {
        const int kn = (kt + 1 < nkt) ? kt + 1 : kt;

        CP_WAIT(1);        // Ks[kt] ready
        __syncthreads();

        // S = Q @ K^T (full 64 keys; Q streamed from L1)
        float sacc[8][4];
#pragma unroll
        for (int nt = 0; nt < 8; nt++)
#pragma unroll
            for (int r = 0; r < 4; r++) sacc[nt][r] = 0.0f;

#pragma unroll
        for (int ch = 0; ch < 8; ch++) {
            const uint4 a0 = *(const uint4*)(Qr0 + ch * 16);
            const uint4 a1 = *(const uint4*)(Qr1 + ch * 16);
#pragma unroll
            for (int nt = 0; nt < 8; nt++) {
                uint4 bf = *(const uint4*)&Ks[(nt * 8 + g) * QROWS + ch * 16 + 4 * tg];
                mma_tf32(sacc[nt][0], sacc[nt][1], sacc[nt][2], sacc[nt][3],
                         a0.x, a1.x, a0.y, a1.y, bf.x, bf.y);
                mma_tf32(sacc[nt][0], sacc[nt][1], sacc[nt][2], sacc[nt][3],
                         a0.z, a1.z, a0.w, a1.w, bf.z, bf.w);
            }
        }

        CP_WAIT(0);        // Vt[kt] ready
        __syncthreads();   // all warps done reading Ks[kt]

        issueK(kn); CP_COMMIT();

        if (kt == qt) {    // diagonal mask
            const int q0 = qt * 64 + pr * 16 + g;
            const int q1 = q0 + 8;
#pragma unroll
            for (int nt = 0; nt < 8; nt++) {
                int k0 = kt * 64 + nt * 8 + 2 * tg;
                if (k0 > q0)     sacc[nt][0] = -1e30f;
                if (k0 + 1 > q0) sacc[nt][1] = -1e30f;
                if (k0 > q1)     sacc[nt][2] = -1e30f;
                if (k0 + 1 > q1) sacc[nt][3] = -1e30f;
            }
        }

        // Global row max (full keys; identical across the pair)
        float mx0 = -1e30f, mx1 = -1e30f;
#pragma unroll
        for (int nt = 0; nt < 8; nt++) {
            mx0 = fmaxf(mx0, fmaxf(sacc[nt][0], sacc[nt][1]));
            mx1 = fmaxf(mx1, fmaxf(sacc[nt][2], sacc[nt][3]));
        }
        mx0 = fmaxf(mx0, __shfl_xor_sync(0xffffffffu, mx0, 1));
        mx0 = fmaxf(mx0, __shfl_xor_sync(0xffffffffu, mx0, 2));
        mx1 = fmaxf(mx1, __shfl_xor_sync(0xffffffffu, mx1, 1));
        mx1 = fmaxf(mx1, __shfl_xor_sync(0xffffffffu, mx1, 2));
        const float nm0 = fmaxf(m0, mx0), nm1 = fmaxf(m1, mx1);
        const float cr0 = __expf(m0 - nm0), cr1 = __expf(m1 - nm1);
        m0 = nm0; m1 = nm1;

        // exp + P write for this warp's key half only
        float s0 = 0.0f, s1 = 0.0f;
        const int ntb = half * 4;
#pragma unroll
        for (int nt2 = 0; nt2 < 4; nt2++) {
            const int nt = ntb + nt2;
#pragma unroll
            for (int jj = 0; jj < 2; jj++) {
                int kk = nt * 8 + 2 * tg + jj;
                int kp = perm16(kk);
                float p0 = __expf(sacc[nt][jj] - nm0);
                s0 += p0;
                Ps[(pr * 16 + g) * PROWS + kp] = f2tf32(p0);
                float p1 = __expf(sacc[nt][2 + jj] - nm1);
                s1 += p1;
                Ps[(pr * 16 + g + 8) * PROWS + kp] = f2tf32(p1);
            }
        }
        s0 += __shfl_xor_sync(0xffffffffu, s0, 1);
        s0 += __shfl_xor_sync(0xffffffffu, s0, 2);
        s1 += __shfl_xor_sync(0xffffffffu, s1, 1);
        s1 += __shfl_xor_sync(0xffffffffu, s1, 2);
        if (tg == 0) {
            Sp[pr * 32 + half * 16 + g * 2 + 0] = s0;
            Sp[pr * 32 + half * 16 + g * 2 + 1] = s1;
        }

        // Pair barrier: P halves + partial sums visible within the pair
        asm volatile("bar.sync %0, 64;" :: "r"(pr + 1) : "memory");

        const float sp0 = Sp[pr * 32 + (1 - half) * 16 + g * 2 + 0];
        const float sp1 = Sp[pr * 32 + (1 - half) * 16 + g * 2 + 1];
        l0 = l0 * cr0 + s0 + sp0;
        l1 = l1 * cr1 + s1 + sp1;

#pragma unroll
        for (int nt = 0; nt < 8; nt++) {
            o[nt][0] *= cr0; o[nt][1] *= cr0;
            o[nt][2] *= cr1; o[nt][3] *= cr1;
        }

        // O += P @ V for this warp's d half (full 64 keys)
#pragma unroll
        for (int ck = 0; ck < 4; ck++) {
            uint4 p0 = *(const uint4*)&Ps[(pr * 16 + g) * PROWS + ck * 16 + 4 * tg];
            uint4 p1 = *(const uint4*)&Ps[(pr * 16 + g + 8) * PROWS + ck * 16 + 4 * tg];
#pragma unroll
            for (int nt = 0; nt < 8; nt++) {
                uint4 bf = *(const uint4*)
                    &Vt[(half * 64 + nt * 8 + g) * VROWS + ck * 16 + 4 * tg];
                mma_tf32(o[nt][0], o[nt][1], o[nt][2], o[nt][3],
                         p0.x, p1.x, p0.y, p1.y, bf.x, bf.y);
                mma_tf32(o[nt][0], o[nt][1], o[nt][2], o[nt][3],
                         p0.z, p1.z, p0.w, p1.w, bf.z, bf.w);
            }
        }

        __syncthreads();           // all Vt/Ps reads done
        issueV(kn); CP_COMMIT();
    }

    const float inv0 = 1.0f / l0, inv1 = 1.0f / l1;
    float* Og = g_AO +
        ((size_t)(b * S_LEN + qt * 64 + pr * 16 + g)) * D_DIM + h * HD;
#pragma unroll
    for (int nt = 0; nt < 8; nt++) {
        const int col = half * 64 + nt * 8 + 2 * tg;
        const int pc0 = perm16(col), pc1 = perm16(col + 1);
        Og[pc0] = __uint_as_float(f2tf32(o[nt][0] * inv0));
        Og[pc1] = __uint_as_float(f2tf32(o[nt][1] * inv0));
        Og[(size_t)8 * D_DIM + pc0] = __uint_as_float(f2tf32(o[nt][2] * inv1));
        Og[(size_t)8 * D_DIM + pc1] = __uint_as_float(f2tf32(o[nt][3] * inv1));
    }
}

// ---------------------------------------------------------------------------
// Launch
// ---------------------------------------------------------------------------
extern "C" void kernel_launch(void* const* d_in, const int* in_sizes, int n_in,
                              void* d_out, int out_size)
{
    const float* x  = (const float*)d_in[0];
    const float* Wq = (const float*)d_in[1];
    const float* bq = (const float*)d_in[2];
    const float* Wk = (const float*)d_in[3];
    const float* bk = (const float*)d_in[4];
    const float* Wv = (const float*)d_in[5];
    const float* bv = (const float*)d_in[6];
    const float* Wo = (const float*)d_in[7];
    const float* bo = (const float*)d_in[8];
    const float* qg = (const float*)d_in[9];
    float* out = (float*)d_out;

    float *Q, *K;
    cudaGetSymbolAddress((void**)&Q, g_Q);
    cudaGetSymbolAddress((void**)&K, g_K);

    const int gemm_smem = 4 * 2048 * 2 * 4;  // 65536
    cudaFuncSetAttribute(gemm_qkv,
                         cudaFuncAttributeMaxDynamicSharedMemorySize, gemm_smem);
    cudaFuncSetAttribute(gemm_out,
                         cudaFuncAttributeMaxDynamicSharedMemorySize, gemm_smem);
    cudaFuncSetAttribute(flash_tf32,
                         cudaFuncAttributeMaxDynamicSharedMemorySize, FL_SMEM);

    // 1. Pre-convert all operands
    convert_all<<<(SEG4 + 255) / 256, 256>>>(x, Wq, Wk, Wv, Wo);

    // 2. Fused Q+K+V projections
    gemm_qkv<<<768, 256, gemm_smem>>>(bq, bk, bv);

    // 3. RMSNorm + RoPE (Q and K in one launch)
    rms_rope_all<<<(RMS_TW / 8), 256>>>(Q, K, qg);

    // 4. Causal flash attention (q-tile 64, 256 thr, 2 CTAs/SM, LPT)
    flash_tf32<<<dim3(S_LEN / 64, B_SZ * NH), 256, FL_SMEM>>>();

    // 5. Output projection
    gemm_out<<<dim3(D_DIM / 128, NTOK / 128), 256, gemm_smem>>>(bo, out);
}

// round 11
// speedup vs baseline: 1.1679x; 1.1679x over previous
#include <cuda_runtime.h>
#include <cstdint>
#include <math.h>

#define S_LEN 2048
#define D_DIM 2048
#define B_SZ  2
#define NH    16
#define NKV   4
#define HD    128
#define NTOK  (B_SZ * S_LEN)   /* 4096 */
#define KVD   (NKV * HD)       /* 512  */
#define EPS_F 1.1920929e-07f

// Scratch (allocation-free rule: __device__ globals)
__device__ float g_Q[(size_t)NTOK * D_DIM];    // tf32+perm after rms_rope
__device__ float g_K[(size_t)NTOK * KVD];
__device__ float g_Vt[(size_t)KVD * NTOK];     // V^T [KVD][NTOK], tok-perm
__device__ float g_AO[(size_t)NTOK * D_DIM];   // tf32+perm (written by flash)
// Pre-converted (tf32-rounded, 16-chunk k-permuted) operands
__device__ float g_xt[(size_t)NTOK * D_DIM];
__device__ float g_Wqt[(size_t)D_DIM * D_DIM];
__device__ float g_Wkt[(size_t)KVD * D_DIM];
__device__ float g_Wvt[(size_t)KVD * D_DIM];
__device__ float g_Wot[(size_t)D_DIM * D_DIM];

__device__ __forceinline__ uint32_t f2tf32(float x) {
    uint32_t r;
    asm("cvt.rna.tf32.f32 %0, %1;" : "=r"(r) : "f"(x));
    return r;
}
__device__ __forceinline__ uint32_t smem_u32(const void* p) {
    uint32_t a;
    asm("{ .reg .u64 t; cvta.to.shared.u64 t, %1; cvt.u32.u64 %0, t; }"
        : "=r"(a) : "l"(p));
    return a;
}
__device__ __forceinline__ int perm16(int c) {
    return (c & ~15) | ((c & 3) << 2) | ((c >> 2) & 3);
}

#define CP_ASYNC16(dst, src) \
    asm volatile("cp.async.cg.shared.global [%0], [%1], 16;" :: "r"(dst), "l"(src))
#define CP_COMMIT() asm volatile("cp.async.commit_group;" ::: "memory")
#define CP_WAIT(n)  asm volatile("cp.async.wait_group %0;" :: "n"(n) : "memory")

// mma.sync m16n8k8 tf32
__device__ __forceinline__ void mma_tf32(
    float& c0, float& c1, float& c2, float& c3,
    uint32_t a0, uint32_t a1, uint32_t a2, uint32_t a3,
    uint32_t b0, uint32_t b1)
{
    asm volatile(
        "mma.sync.aligned.m16n8k8.row.col.f32.tf32.tf32.f32 "
        "{%0,%1,%2,%3}, {%4,%5,%6,%7}, {%8,%9}, {%0,%1,%2,%3};"
        : "+f"(c0), "+f"(c1), "+f"(c2), "+f"(c3)
        : "r"(a0), "r"(a1), "r"(a2), "r"(a3), "r"(b0), "r"(b1));
}

// ---------------------------------------------------------------------------
// Segmented convert: fp32 -> tf32(rna) + 16-chunk k-perm, one launch.
// ---------------------------------------------------------------------------
#define N4_X  (NTOK * D_DIM / 4)
#define N4_WQ (D_DIM * D_DIM / 4)
#define N4_WK (KVD * D_DIM / 4)
#define SEG0 (N4_X)
#define SEG1 (SEG0 + N4_WQ)
#define SEG2 (SEG1 + N4_WK)
#define SEG3 (SEG2 + N4_WK)
#define SEG4 (SEG3 + N4_WQ)

__global__ __launch_bounds__(256) void convert_all(
    const float* __restrict__ x,  const float* __restrict__ Wq,
    const float* __restrict__ Wk, const float* __restrict__ Wv,
    const float* __restrict__ Wo)
{
    int i = blockIdx.x * 256 + threadIdx.x;
    if (i >= SEG4) return;
    const float* src;
    float* dst;
    int j;
    if (i < SEG0)      { src = x;  dst = g_xt;  j = i; }
    else if (i < SEG1) { src = Wq; dst = g_Wqt; j = i - SEG0; }
    else if (i < SEG2) { src = Wk; dst = g_Wkt; j = i - SEG1; }
    else if (i < SEG3) { src = Wv; dst = g_Wvt; j = i - SEG2; }
    else               { src = Wo; dst = g_Wot; j = i - SEG3; }
    float4 v = ((const float4*)src)[j];
    int f0 = j << 2;
    int base = f0 & ~15;
    int q = (f0 >> 2) & 3;
    dst[base + 0 + q]  = __uint_as_float(f2tf32(v.x));
    dst[base + 4 + q]  = __uint_as_float(f2tf32(v.y));
    dst[base + 8 + q]  = __uint_as_float(f2tf32(v.z));
    dst[base + 12 + q] = __uint_as_float(f2tf32(v.w));
}

// ---------------------------------------------------------------------------
// Shared GEMM body: 128x128 tile, 4-stage cp.async, BK=16.
// ---------------------------------------------------------------------------
struct GemmJob {
    const float* Ap;
    const float* Bp;
    const float* bias;
    float* C;
    int N, K, rowBase, colBase, vmode;
};

__device__ __forceinline__ void gemm_body(const GemmJob& jb, float* gsm)
{
    float* sA = gsm;
    float* sB = gsm + 4 * 2048;
    const uint32_t sAu = smem_u32(sA);
    const uint32_t sBu = smem_u32(sB);

    const int tid = threadIdx.x;
    const int lane = tid & 31, wid = tid >> 5;
    const int wm = wid >> 1, wn = wid & 1;
    const int g = lane >> 2, tg = lane & 3;
    const int lrow = tid >> 2;
    const int lc4 = tid & 3;
    const int K = jb.K;

    float acc[2][8][4];
#pragma unroll
    for (int mt = 0; mt < 2; mt++)
#pragma unroll
        for (int nt = 0; nt < 8; nt++)
#pragma unroll
            for (int r = 0; r < 4; r++) acc[mt][nt][r] = 0.0f;

    const int NT = K >> 4;

    auto issue = [&](int slot, int t) {
#pragma unroll
        for (int p = 0; p < 2; p++) {
            const int row = lrow + p * 64;
            const size_t go = (size_t)row * K + t * 16 + lc4 * 4;
            const uint32_t so = (uint32_t)((slot * 2048 + row * 16 + lc4 * 4) * 4);
            CP_ASYNC16(sAu + so, jb.Ap + go);
            CP_ASYNC16(sBu + so, jb.Bp + go);
        }
    };

#pragma unroll
    for (int s = 0; s < 3; s++) { issue(s, s); CP_COMMIT(); }

    for (int t = 0; t < NT; t++) {
        CP_WAIT(2);
        __syncthreads();
        const int tn = t + 3;
        if (tn < NT) issue(tn & 3, tn);
        CP_COMMIT();

        const float* bA = sA + (t & 3) * 2048;
        const float* bB = sB + (t & 3) * 2048;

        uint4 afr[2][2];
#pragma unroll
        for (int mt = 0; mt < 2; mt++) {
            const int r0 = wm * 32 + mt * 16 + g;
            afr[mt][0] = *(const uint4*)&bA[r0 * 16 + 4 * tg];
            afr[mt][1] = *(const uint4*)&bA[(r0 + 8) * 16 + 4 * tg];
        }
        uint4 bfr[8];
#pragma unroll
        for (int nt = 0; nt < 8; nt++)
            bfr[nt] = *(const uint4*)&bB[(wn * 64 + nt * 8 + g) * 16 + 4 * tg];

#pragma unroll
        for (int mt = 0; mt < 2; mt++)
#pragma unroll
            for (int nt = 0; nt < 8; nt++)
                mma_tf32(acc[mt][nt][0], acc[mt][nt][1], acc[mt][nt][2], acc[mt][nt][3],
                         afr[mt][0].x, afr[mt][1].x, afr[mt][0].y, afr[mt][1].y,
                         bfr[nt].x, bfr[nt].y);
#pragma unroll
        for (int mt = 0; mt < 2; mt++)
#pragma unroll
            for (int nt = 0; nt < 8; nt++)
                mma_tf32(acc[mt][nt][0], acc[mt][nt][1], acc[mt][nt][2], acc[mt][nt][3],
                         afr[mt][0].z, afr[mt][1].z, afr[mt][0].w, afr[mt][1].w,
                         bfr[nt].z, bfr[nt].w);
    }

    if (!jb.vmode) {
#pragma unroll
        for (int mt = 0; mt < 2; mt++) {
            const int row = jb.rowBase + wm * 32 + mt * 16 + g;
#pragma unroll
            for (int nt = 0; nt < 8; nt++) {
                const int col = jb.colBase + wn * 64 + nt * 8 + 2 * tg;
                const float2 bb = *(const float2*)(jb.bias + col);
                float2 o0, o1;
                o0.x = acc[mt][nt][0] + bb.x;
                o0.y = acc[mt][nt][1] + bb.y;
                o1.x = acc[mt][nt][2] + bb.x;
                o1.y = acc[mt][nt][3] + bb.y;
                *(float2*)(jb.C + (size_t)row * jb.N + col) = o0;
                *(float2*)(jb.C + (size_t)(row + 8) * jb.N + col) = o1;
            }
        }
    } else {
#pragma unroll
        for (int mt = 0; mt < 2; mt++) {
            const int r = jb.rowBase + wm * 32 + mt * 16 + g;
            const int rp0 = perm16(r);
            const int rp1 = perm16(r + 8);
#pragma unroll
            for (int nt = 0; nt < 8; nt++) {
                const int col = jb.colBase + wn * 64 + nt * 8 + 2 * tg;
                const float b0 = jb.bias[col], b1 = jb.bias[col + 1];
                jb.C[(size_t)col * NTOK + rp0] =
                    __uint_as_float(f2tf32(acc[mt][nt][0] + b0));
                jb.C[(size_t)(col + 1) * NTOK + rp0] =
                    __uint_as_float(f2tf32(acc[mt][nt][1] + b1));
                jb.C[(size_t)col * NTOK + rp1] =
                    __uint_as_float(f2tf32(acc[mt][nt][2] + b0));
                jb.C[(size_t)(col + 1) * NTOK + rp1] =
                    __uint_as_float(f2tf32(acc[mt][nt][3] + b1));
            }
        }
    }
}

// ---------------------------------------------------------------------------
// Fused Q+K+V projection, one launch, flat 768-block grid.
// ---------------------------------------------------------------------------
__global__ __launch_bounds__(256) void gemm_qkv(
    const float* __restrict__ bq, const float* __restrict__ bk,
    const float* __restrict__ bv)
{
    extern __shared__ __align__(16) float gsm[];
    GemmJob jb;
    jb.K = D_DIM;
    const int blk = blockIdx.x;
    if (blk < 512) {
        jb.rowBase = (blk >> 4) * 128; jb.colBase = (blk & 15) * 128;
        jb.Bp = g_Wqt + (size_t)jb.colBase * D_DIM;
        jb.bias = bq; jb.C = g_Q; jb.N = D_DIM; jb.vmode = 0;
    } else if (blk < 640) {
        const int t = blk - 512;
        jb.rowBase = (t >> 2) * 128; jb.colBase = (t & 3) * 128;
        jb.Bp = g_Wkt + (size_t)jb.colBase * D_DIM;
        jb.bias = bk; jb.C = g_K; jb.N = KVD; jb.vmode = 0;
    } else {
        const int t = blk - 640;
        jb.rowBase = (t >> 2) * 128; jb.colBase = (t & 3) * 128;
        jb.Bp = g_Wvt + (size_t)jb.colBase * D_DIM;
        jb.bias = bv; jb.C = g_Vt; jb.N = KVD; jb.vmode = 1;
    }
    jb.Ap = g_xt + (size_t)jb.rowBase * D_DIM;
    gemm_body(jb, gsm);
}

__global__ __launch_bounds__(256) void gemm_out(
    const float* __restrict__ bias, float* __restrict__ C)
{
    extern __shared__ __align__(16) float gsm[];
    GemmJob jb;
    jb.K = D_DIM;
    jb.rowBase = blockIdx.y * 128;
    jb.colBase = blockIdx.x * 128;
    jb.Ap = g_AO + (size_t)jb.rowBase * D_DIM;
    jb.Bp = g_Wot + (size_t)jb.colBase * D_DIM;
    jb.bias = bias; jb.C = C; jb.N = D_DIM; jb.vmode = 0;
    gemm_body(jb, gsm);
}

// ---------------------------------------------------------------------------
// Fused RMSNorm + RoPE for Q and K in one launch; writes tf32+perm in place.
// ---------------------------------------------------------------------------
#define RMS_QW (NTOK * NH)
#define RMS_TW (NTOK * (NH + NKV))

__global__ __launch_bounds__(256) void rms_rope_all(
    float* __restrict__ Q, float* __restrict__ K,
    const float* __restrict__ gain)
{
    int gw = (blockIdx.x * blockDim.x + threadIdx.x) >> 5;
    int lane = threadIdx.x & 31;
    if (gw >= RMS_TW) return;

    float* p;
    int token;
    float gmul;
    if (gw < RMS_QW) {
        token = gw >> 4;
        int h = gw & 15;
        p = Q + (size_t)token * D_DIM + h * HD;
        gmul = gain[h] * 0.088388347648318447f;
    } else {
        int gw2 = gw - RMS_QW;
        token = gw2 >> 2;
        int h = gw2 & 3;
        p = K + (size_t)token * KVD + h * HD;
        gmul = 1.0f;
    }

    float a1 = p[lane];
    float b1 = p[lane + 32];
    float a2 = p[lane + 64];
    float b2 = p[lane + 96];

    float ss = a1 * a1 + b1 * b1 + a2 * a2 + b2 * b2;
#pragma unroll
    for (int off = 16; off; off >>= 1)
        ss += __shfl_xor_sync(0xffffffffu, ss, off);

    float g = rsqrtf(ss * (1.0f / 128.0f) + EPS_F) * gmul;

    int pos = token & (S_LEN - 1);
    const float c = -0.20762050593046015f;  // -log2(10000)/64
    float invfa = exp2f(c * (float)lane);
    float invfb = exp2f(c * (float)(lane + 32));
    float sa, ca, sb, cb;
    sincosf((float)pos * invfa, &sa, &ca);
    sincosf((float)pos * invfb, &sb, &cb);

    p[perm16(lane)]      = __uint_as_float(f2tf32((a1 * ca + a2 * sa) * g));
    p[perm16(lane + 64)] = __uint_as_float(f2tf32((a2 * ca - a1 * sa) * g));
    p[perm16(lane + 32)] = __uint_as_float(f2tf32((b1 * cb + b2 * sb) * g));
    p[perm16(lane + 96)] = __uint_as_float(f2tf32((b2 * cb - b1 * sb) * g));
}

// ---------------------------------------------------------------------------
// Causal flash attention v5: q-tile 64, 256 threads (8 warps), 2 CTAs/SM.
// Warp pair pr owns 16 q-rows. NO duplication:
//   QK^T split by key-half (each warp its 32 keys, sacc[4][4])
//   softmax: pair-exchange of half-max, then half-sum (2 x bar.sync(64))
//   PV split by d-half (each warp 64 d over all 64 keys)
// Q streamed from gmem/L1. Chip mma count identical to R8.
// ---------------------------------------------------------------------------
#define QROWS 132
#define VROWS 68
#define PROWS 68
#define FL_SMEM ((64 * QROWS + 128 * VROWS + 64 * PROWS + 512) * 4)  /* 88064 */

__global__ __launch_bounds__(256, 2) void flash_tf32()
{
    extern __shared__ __align__(16) uint32_t usm[];
    uint32_t* Ks = usm;                    // [64][QROWS]
    uint32_t* Vt = Ks + 64 * QROWS;        // [128][VROWS]
    uint32_t* Ps = Vt + 128 * VROWS;       // [64][PROWS]
    float* Smx = (float*)(Ps + 64 * PROWS);     // [4 pair][2 half][2][16] max
    float* Ssm = Smx + 256;                     // [4 pair][2 half][2][16] sum
    const uint32_t Ksu = smem_u32(Ks);
    const uint32_t Vtu = smem_u32(Vt);

    const int qt = gridDim.x - 1 - blockIdx.x;   // LPT
    const int bh = blockIdx.y;
    const int b = bh >> 4, h = bh & 15, kvh = h >> 2;
    const int tid = threadIdx.x;
    const int lane = tid & 31, w = tid >> 5;
    const int pr = w >> 1, half = w & 1;
    const int g = lane >> 2, tg = lane & 3;

    const float* Kg = g_K + ((size_t)b * S_LEN) * KVD + kvh * HD;
    const float* Vg = g_Vt + (size_t)(kvh * HD) * NTOK + b * S_LEN;

    // Loaders: 256 threads, 8 x cp.async(16B) each per tile.
    const int krow = tid >> 2, kq = tid & 3;     // K: [64][128]
    const int vd = tid >> 1, vh = tid & 1;       // Vt: [128][64]
    auto issueK = [&](int kt) {
        const float* src = Kg + (size_t)(kt * 64 + krow) * KVD + kq * 32;
        const uint32_t dst = Ksu + (uint32_t)((krow * QROWS + kq * 32) * 4);
#pragma unroll
        for (int i = 0; i < 8; i++)
            CP_ASYNC16(dst + i * 16, src + i * 4);
    };
    auto issueV = [&](int kt) {
        const float* src = Vg + (size_t)vd * NTOK + kt * 64 + vh * 32;
        const uint32_t dst = Vtu + (uint32_t)((vd * VROWS + vh * 32) * 4);
#pragma unroll
        for (int i = 0; i < 8; i++)
            CP_ASYNC16(dst + i * 16, src + i * 4);
    };

    const int nkt = qt + 1;
    issueK(0); CP_COMMIT();
    issueV(0); CP_COMMIT();

    // Q row pointers (tf32+permuted in gmem; streamed via L1 each tile)
    const float* Qr0 = g_Q +
        ((size_t)(b * S_LEN + qt * 64 + pr * 16 + g)) * D_DIM + h * HD + 4 * tg;
    const float* Qr1 = Qr0 + 8 * D_DIM;

    float o[8][4];
#pragma unroll
    for (int nt = 0; nt < 8; nt++)
#pragma unroll
        for (int r = 0; r < 4; r++) o[nt][r] = 0.0f;
    float m0 = -1e30f, m1 = -1e30f, l0 = 0.0f, l1 = 0.0f;

    const int ntb = half * 4;                  // this warp's key quarter base
    float* myMx = Smx + (pr * 2 + half) * 32;
    float* otMx = Smx + (pr * 2 + (1 - half)) * 32;
    float* mySm = Ssm + (pr * 2 + half) * 32;
    float* otSm = Ssm + (pr * 2 + (1 - half)) * 32;

    for (int kt = 0; kt < nkt; kt++) {
        const int kn = (kt + 1 < nkt) ? kt + 1 : kt;

        CP_WAIT(1);        // Ks[kt] ready
        __syncthreads();

        // S = Q @ K^T for THIS warp's 32-key half only (no duplication)
        float sacc[4][4];
#pragma unroll
        for (int nt2 = 0; nt2 < 4; nt2++)
#pragma unroll
            for (int r = 0; r < 4; r++) sacc[nt2][r] = 0.0f;

#pragma unroll
        for (int ch = 0; ch < 8; ch++) {
            const uint4 a0 = *(const uint4*)(Qr0 + ch * 16);
            const uint4 a1 = *(const uint4*)(Qr1 + ch * 16);
#pragma unroll
            for (int nt2 = 0; nt2 < 4; nt2++) {
                const int nt = ntb + nt2;
                uint4 bf = *(const uint4*)&Ks[(nt * 8 + g) * QROWS + ch * 16 + 4 * tg];
                mma_tf32(sacc[nt2][0], sacc[nt2][1], sacc[nt2][2], sacc[nt2][3],
                         a0.x, a1.x, a0.y, a1.y, bf.x, bf.y);
                mma_tf32(sacc[nt2][0], sacc[nt2][1], sacc[nt2][2], sacc[nt2][3],
                         a0.z, a1.z, a0.w, a1.w, bf.z, bf.w);
            }
        }

        CP_WAIT(0);        // Vt[kt] ready
        __syncthreads();   // all warps done reading Ks[kt]

        issueK(kn); CP_COMMIT();

        if (kt == qt) {    // diagonal mask (this warp's keys)
            const int q0 = qt * 64 + pr * 16 + g;
            const int q1 = q0 + 8;
#pragma unroll
            for (int nt2 = 0; nt2 < 4; nt2++) {
                int k0 = kt * 64 + (ntb + nt2) * 8 + 2 * tg;
                if (k0 > q0)     sacc[nt2][0] = -1e30f;
                if (k0 + 1 > q0) sacc[nt2][1] = -1e30f;
                if (k0 > q1)     sacc[nt2][2] = -1e30f;
                if (k0 + 1 > q1) sacc[nt2][3] = -1e30f;
            }
        }

        // Half-max over this warp's 32 keys
        float mx0 = -1e30f, mx1 = -1e30f;
#pragma unroll
        for (int nt2 = 0; nt2 < 4; nt2++) {
            mx0 = fmaxf(mx0, fmaxf(sacc[nt2][0], sacc[nt2][1]));
            mx1 = fmaxf(mx1, fmaxf(sacc[nt2][2], sacc[nt2][3]));
        }
        mx0 = fmaxf(mx0, __shfl_xor_sync(0xffffffffu, mx0, 1));
        mx0 = fmaxf(mx0, __shfl_xor_sync(0xffffffffu, mx0, 2));
        mx1 = fmaxf(mx1, __shfl_xor_sync(0xffffffffu, mx1, 1));
        mx1 = fmaxf(mx1, __shfl_xor_sync(0xffffffffu, mx1, 2));

        // Pair exchange #1: half-max -> global row max
        if (tg == 0) { myMx[g] = mx0; myMx[16 + g] = mx1; }
        asm volatile("bar.sync %0, 64;" :: "r"(pr + 1) : "memory");
        const float gmx0 = fmaxf(mx0, otMx[g]);
        const float gmx1 = fmaxf(mx1, otMx[16 + g]);

        const float nm0 = fmaxf(m0, gmx0), nm1 = fmaxf(m1, gmx1);
        const float cr0 = __expf(m0 - nm0), cr1 = __expf(m1 - nm1);
        m0 = nm0; m1 = nm1;

        // exp + P write for this warp's key half
        float s0 = 0.0f, s1 = 0.0f;
#pragma unroll
        for (int nt2 = 0; nt2 < 4; nt2++) {
            const int nt = ntb + nt2;
#pragma unroll
            for (int jj = 0; jj < 2; jj++) {
                int kk = nt * 8 + 2 * tg + jj;
                int kp = perm16(kk);
                float p0 = __expf(sacc[nt2][jj] - nm0);
                s0 += p0;
                Ps[(pr * 16 + g) * PROWS + kp] = f2tf32(p0);
                float p1 = __expf(sacc[nt2][2 + jj] - nm1);
                s1 += p1;
                Ps[(pr * 16 + g + 8) * PROWS + kp] = f2tf32(p1);
            }
        }
        s0 += __shfl_xor_sync(0xffffffffu, s0, 1);
        s0 += __shfl_xor_sync(0xffffffffu, s0, 2);
        s1 += __shfl_xor_sync(0xffffffffu, s1, 1);
        s1 += __shfl_xor_sync(0xffffffffu, s1, 2);
        if (tg == 0) { mySm[g] = s0; mySm[16 + g] = s1; }

        // Pair exchange #2: P halves + partial sums visible
        asm volatile("bar.sync %0, 64;" :: "r"(pr + 1) : "memory");
        l0 = l0 * cr0 + s0 + otSm[g];
        l1 = l1 * cr1 + s1 + otSm[16 + g];

#pragma unroll
        for (int nt = 0; nt < 8; nt++) {
            o[nt][0] *= cr0; o[nt][1] *= cr0;
            o[nt][2] *= cr1; o[nt][3] *= cr1;
        }

        // O += P @ V for this warp's d half (full 64 keys)
#pragma unroll
        for (int ck = 0; ck < 4; ck++) {
            uint4 p0 = *(const uint4*)&Ps[(pr * 16 + g) * PROWS + ck * 16 + 4 * tg];
            uint4 p1 = *(const uint4*)&Ps[(pr * 16 + g + 8) * PROWS + ck * 16 + 4 * tg];
#pragma unroll
            for (int nt = 0; nt < 8; nt++) {
                uint4 bf = *(const uint4*)
                    &Vt[(half * 64 + nt * 8 + g) * VROWS + ck * 16 + 4 * tg];
                mma_tf32(o[nt][0], o[nt][1], o[nt][2], o[nt][3],
                         p0.x, p1.x, p0.y, p1.y, bf.x, bf.y);
                mma_tf32(o[nt][0], o[nt][1], o[nt][2], o[nt][3],
                         p0.z, p1.z, p0.w, p1.w, bf.z, bf.w);
            }
        }

        __syncthreads();           // all Vt/Ps reads done
        issueV(kn); CP_COMMIT();
    }

    const float inv0 = 1.0f / l0, inv1 = 1.0f / l1;
    float* Og = g_AO +
        ((size_t)(b * S_LEN + qt * 64 + pr * 16 + g)) * D_DIM + h * HD;
#pragma unroll
    for (int nt = 0; nt < 8; nt++) {
        const int col = half * 64 + nt * 8 + 2 * tg;
        const int pc0 = perm16(col), pc1 = perm16(col + 1);
        Og[pc0] = __uint_as_float(f2tf32(o[nt][0] * inv0));
        Og[pc1] = __uint_as_float(f2tf32(o[nt][1] * inv0));
        Og[(size_t)8 * D_DIM + pc0] = __uint_as_float(f2tf32(o[nt][2] * inv1));
        Og[(size_t)8 * D_DIM + pc1] = __uint_as_float(f2tf32(o[nt][3] * inv1));
    }
}

// ---------------------------------------------------------------------------
// Launch
// ---------------------------------------------------------------------------
extern "C" void kernel_launch(void* const* d_in, const int* in_sizes, int n_in,
                              void* d_out, int out_size)
{
    const float* x  = (const float*)d_in[0];
    const float* Wq = (const float*)d_in[1];
    const float* bq = (const float*)d_in[2];
    const float* Wk = (const float*)d_in[3];
    const float* bk = (const float*)d_in[4];
    const float* Wv = (const float*)d_in[5];
    const float* bv = (const float*)d_in[6];
    const float* Wo = (const float*)d_in[7];
    const float* bo = (const float*)d_in[8];
    const float* qg = (const float*)d_in[9];
    float* out = (float*)d_out;

    float *Q, *K;
    cudaGetSymbolAddress((void**)&Q, g_Q);
    cudaGetSymbolAddress((void**)&K, g_K);

    const int gemm_smem = 4 * 2048 * 2 * 4;  // 65536
    cudaFuncSetAttribute(gemm_qkv,
                         cudaFuncAttributeMaxDynamicSharedMemorySize, gemm_smem);
    cudaFuncSetAttribute(gemm_out,
                         cudaFuncAttributeMaxDynamicSharedMemorySize, gemm_smem);
    cudaFuncSetAttribute(flash_tf32,
                         cudaFuncAttributeMaxDynamicSharedMemorySize, FL_SMEM);

    // 1. Pre-convert all operands
    convert_all<<<(SEG4 + 255) / 256, 256>>>(x, Wq, Wk, Wv, Wo);

    // 2. Fused Q+K+V projections
    gemm_qkv<<<768, 256, gemm_smem>>>(bq, bk, bv);

    // 3. RMSNorm + RoPE (Q and K in one launch)
    rms_rope_all<<<(RMS_TW / 8), 256>>>(Q, K, qg);

    // 4. Causal flash attention (v5: key-split pairs, 2 CTAs/SM, LPT)
    flash_tf32<<<dim3(S_LEN / 64, B_SZ * NH), 256, FL_SMEM>>>();

    // 5. Output projection
    gemm_out<<<dim3(D_DIM / 128, NTOK / 128), 256, gemm_smem>>>(bo, out);
}

// round 12
// speedup vs baseline: 1.2836x; 1.0991x over previous
#include <cuda_runtime.h>
#include <cstdint>
#include <math.h>

#define S_LEN 2048
#define D_DIM 2048
#define B_SZ  2
#define NH    16
#define NKV   4
#define HD    128
#define NTOK  (B_SZ * S_LEN)   /* 4096 */
#define KVD   (NKV * HD)       /* 512  */
#define EPS_F 1.1920929e-07f

// Scratch (allocation-free rule: __device__ globals)
__device__ float g_Q[(size_t)NTOK * D_DIM];    // tf32+perm after rms_rope
__device__ float g_K[(size_t)NTOK * KVD];
__device__ float g_Vt[(size_t)KVD * NTOK];     // V^T [KVD][NTOK], tok-perm
__device__ float g_AO[(size_t)NTOK * D_DIM];   // tf32+perm (written by flash)
// Pre-converted (tf32-rounded, 16-chunk k-permuted) operands
__device__ float g_xt[(size_t)NTOK * D_DIM];
__device__ float g_Wqt[(size_t)D_DIM * D_DIM];
__device__ float g_Wkt[(size_t)KVD * D_DIM];
__device__ float g_Wvt[(size_t)KVD * D_DIM];
__device__ float g_Wot[(size_t)D_DIM * D_DIM];

__device__ __forceinline__ uint32_t f2tf32(float x) {
    uint32_t r;
    asm("cvt.rna.tf32.f32 %0, %1;" : "=r"(r) : "f"(x));
    return r;
}
__device__ __forceinline__ uint32_t smem_u32(const void* p) {
    uint32_t a;
    asm("{ .reg .u64 t; cvta.to.shared.u64 t, %1; cvt.u32.u64 %0, t; }"
        : "=r"(a) : "l"(p));
    return a;
}
__device__ __forceinline__ int perm16(int c) {
    return (c & ~15) | ((c & 3) << 2) | ((c >> 2) & 3);
}

#define CP_ASYNC16(dst, src) \
    asm volatile("cp.async.cg.shared.global [%0], [%1], 16;" :: "r"(dst), "l"(src))
#define CP_COMMIT() asm volatile("cp.async.commit_group;" ::: "memory")
#define CP_WAIT(n)  asm volatile("cp.async.wait_group %0;" :: "n"(n) : "memory")

// mma.sync m16n8k8 tf32
__device__ __forceinline__ void mma_tf32(
    float& c0, float& c1, float& c2, float& c3,
    uint32_t a0, uint32_t a1, uint32_t a2, uint32_t a3,
    uint32_t b0, uint32_t b1)
{
    asm volatile(
        "mma.sync.aligned.m16n8k8.row.col.f32.tf32.tf32.f32 "
        "{%0,%1,%2,%3}, {%4,%5,%6,%7}, {%8,%9}, {%0,%1,%2,%3};"
        : "+f"(c0), "+f"(c1), "+f"(c2), "+f"(c3)
        : "r"(a0), "r"(a1), "r"(a2), "r"(a3), "r"(b0), "r"(b1));
}

// ---------------------------------------------------------------------------
// Segmented convert: fp32 -> tf32(rna) + 16-chunk k-perm, one launch.
// ---------------------------------------------------------------------------
#define N4_X  (NTOK * D_DIM / 4)
#define N4_WQ (D_DIM * D_DIM / 4)
#define N4_WK (KVD * D_DIM / 4)
#define SEG0 (N4_X)
#define SEG1 (SEG0 + N4_WQ)
#define SEG2 (SEG1 + N4_WK)
#define SEG3 (SEG2 + N4_WK)
#define SEG4 (SEG3 + N4_WQ)

__global__ __launch_bounds__(256) void convert_all(
    const float* __restrict__ x,  const float* __restrict__ Wq,
    const float* __restrict__ Wk, const float* __restrict__ Wv,
    const float* __restrict__ Wo)
{
    int i = blockIdx.x * 256 + threadIdx.x;
    if (i >= SEG4) return;
    const float* src;
    float* dst;
    int j;
    if (i < SEG0)      { src = x;  dst = g_xt;  j = i; }
    else if (i < SEG1) { src = Wq; dst = g_Wqt; j = i - SEG0; }
    else if (i < SEG2) { src = Wk; dst = g_Wkt; j = i - SEG1; }
    else if (i < SEG3) { src = Wv; dst = g_Wvt; j = i - SEG2; }
    else               { src = Wo; dst = g_Wot; j = i - SEG3; }
    float4 v = ((const float4*)src)[j];
    int f0 = j << 2;
    int base = f0 & ~15;
    int q = (f0 >> 2) & 3;
    dst[base + 0 + q]  = __uint_as_float(f2tf32(v.x));
    dst[base + 4 + q]  = __uint_as_float(f2tf32(v.y));
    dst[base + 8 + q]  = __uint_as_float(f2tf32(v.z));
    dst[base + 12 + q] = __uint_as_float(f2tf32(v.w));
}

// ---------------------------------------------------------------------------
// Shared GEMM body: 128x128 tile, 4-stage cp.async, BK=16.
// ---------------------------------------------------------------------------
struct GemmJob {
    const float* Ap;
    const float* Bp;
    const float* bias;
    float* C;
    int N, K, rowBase, colBase, vmode;
};

__device__ __forceinline__ void gemm_body(const GemmJob& jb, float* gsm)
{
    float* sA = gsm;
    float* sB = gsm + 4 * 2048;
    const uint32_t sAu = smem_u32(sA);
    const uint32_t sBu = smem_u32(sB);

    const int tid = threadIdx.x;
    const int lane = tid & 31, wid = tid >> 5;
    const int wm = wid >> 1, wn = wid & 1;
    const int g = lane >> 2, tg = lane & 3;
    const int lrow = tid >> 2;
    const int lc4 = tid & 3;
    const int K = jb.K;

    float acc[2][8][4];
#pragma unroll
    for (int mt = 0; mt < 2; mt++)
#pragma unroll
        for (int nt = 0; nt < 8; nt++)
#pragma unroll
            for (int r = 0; r < 4; r++) acc[mt][nt][r] = 0.0f;

    const int NT = K >> 4;

    auto issue = [&](int slot, int t) {
#pragma unroll
        for (int p = 0; p < 2; p++) {
            const int row = lrow + p * 64;
            const size_t go = (size_t)row * K + t * 16 + lc4 * 4;
            const uint32_t so = (uint32_t)((slot * 2048 + row * 16 + lc4 * 4) * 4);
            CP_ASYNC16(sAu + so, jb.Ap + go);
            CP_ASYNC16(sBu + so, jb.Bp + go);
        }
    };

#pragma unroll
    for (int s = 0; s < 3; s++) { issue(s, s); CP_COMMIT(); }

    for (int t = 0; t < NT; t++) {
        CP_WAIT(2);
        __syncthreads();
        const int tn = t + 3;
        if (tn < NT) issue(tn & 3, tn);
        CP_COMMIT();

        const float* bA = sA + (t & 3) * 2048;
        const float* bB = sB + (t & 3) * 2048;

        uint4 afr[2][2];
#pragma unroll
        for (int mt = 0; mt < 2; mt++) {
            const int r0 = wm * 32 + mt * 16 + g;
            afr[mt][0] = *(const uint4*)&bA[r0 * 16 + 4 * tg];
            afr[mt][1] = *(const uint4*)&bA[(r0 + 8) * 16 + 4 * tg];
        }
        uint4 bfr[8];
#pragma unroll
        for (int nt = 0; nt < 8; nt++)
            bfr[nt] = *(const uint4*)&bB[(wn * 64 + nt * 8 + g) * 16 + 4 * tg];

#pragma unroll
        for (int mt = 0; mt < 2; mt++)
#pragma unroll
            for (int nt = 0; nt < 8; nt++)
                mma_tf32(acc[mt][nt][0], acc[mt][nt][1], acc[mt][nt][2], acc[mt][nt][3],
                         afr[mt][0].x, afr[mt][1].x, afr[mt][0].y, afr[mt][1].y,
                         bfr[nt].x, bfr[nt].y);
#pragma unroll
        for (int mt = 0; mt < 2; mt++)
#pragma unroll
            for (int nt = 0; nt < 8; nt++)
                mma_tf32(acc[mt][nt][0], acc[mt][nt][1], acc[mt][nt][2], acc[mt][nt][3],
                         afr[mt][0].z, afr[mt][1].z, afr[mt][0].w, afr[mt][1].w,
                         bfr[nt].z, bfr[nt].w);
    }

    if (!jb.vmode) {
#pragma unroll
        for (int mt = 0; mt < 2; mt++) {
            const int row = jb.rowBase + wm * 32 + mt * 16 + g;
#pragma unroll
            for (int nt = 0; nt < 8; nt++) {
                const int col = jb.colBase + wn * 64 + nt * 8 + 2 * tg;
                const float2 bb = *(const float2*)(jb.bias + col);
                float2 o0, o1;
                o0.x = acc[mt][nt][0] + bb.x;
                o0.y = acc[mt][nt][1] + bb.y;
                o1.x = acc[mt][nt][2] + bb.x;
                o1.y = acc[mt][nt][3] + bb.y;
                *(float2*)(jb.C + (size_t)row * jb.N + col) = o0;
                *(float2*)(jb.C + (size_t)(row + 8) * jb.N + col) = o1;
            }
        }
    } else {
#pragma unroll
        for (int mt = 0; mt < 2; mt++) {
            const int r = jb.rowBase + wm * 32 + mt * 16 + g;
            const int rp0 = perm16(r);
            const int rp1 = perm16(r + 8);
#pragma unroll
            for (int nt = 0; nt < 8; nt++) {
                const int col = jb.colBase + wn * 64 + nt * 8 + 2 * tg;
                const float b0 = jb.bias[col], b1 = jb.bias[col + 1];
                jb.C[(size_t)col * NTOK + rp0] =
                    __uint_as_float(f2tf32(acc[mt][nt][0] + b0));
                jb.C[(size_t)(col + 1) * NTOK + rp0] =
                    __uint_as_float(f2tf32(acc[mt][nt][1] + b1));
                jb.C[(size_t)col * NTOK + rp1] =
                    __uint_as_float(f2tf32(acc[mt][nt][2] + b0));
                jb.C[(size_t)(col + 1) * NTOK + rp1] =
                    __uint_as_float(f2tf32(acc[mt][nt][3] + b1));
            }
        }
    }
}

// ---------------------------------------------------------------------------
// Fused Q+K+V projection, one launch, flat 768-block grid.
// ---------------------------------------------------------------------------
__global__ __launch_bounds__(256) void gemm_qkv(
    const float* __restrict__ bq, const float* __restrict__ bk,
    const float* __restrict__ bv)
{
    extern __shared__ __align__(16) float gsm[];
    GemmJob jb;
    jb.K = D_DIM;
    const int blk = blockIdx.x;
    if (blk < 512) {
        jb.rowBase = (blk >> 4) * 128; jb.colBase = (blk & 15) * 128;
        jb.Bp = g_Wqt + (size_t)jb.colBase * D_DIM;
        jb.bias = bq; jb.C = g_Q; jb.N = D_DIM; jb.vmode = 0;
    } else if (blk < 640) {
        const int t = blk - 512;
        jb.rowBase = (t >> 2) * 128; jb.colBase = (t & 3) * 128;
        jb.Bp = g_Wkt + (size_t)jb.colBase * D_DIM;
        jb.bias = bk; jb.C = g_K; jb.N = KVD; jb.vmode = 0;
    } else {
        const int t = blk - 640;
        jb.rowBase = (t >> 2) * 128; jb.colBase = (t & 3) * 128;
        jb.Bp = g_Wvt + (size_t)jb.colBase * D_DIM;
        jb.bias = bv; jb.C = g_Vt; jb.N = KVD; jb.vmode = 1;
    }
    jb.Ap = g_xt + (size_t)jb.rowBase * D_DIM;
    gemm_body(jb, gsm);
}

__global__ __launch_bounds__(256) void gemm_out(
    const float* __restrict__ bias, float* __restrict__ C)
{
    extern __shared__ __align__(16) float gsm[];
    GemmJob jb;
    jb.K = D_DIM;
    jb.rowBase = blockIdx.y * 128;
    jb.colBase = blockIdx.x * 128;
    jb.Ap = g_AO + (size_t)jb.rowBase * D_DIM;
    jb.Bp = g_Wot + (size_t)jb.colBase * D_DIM;
    jb.bias = bias; jb.C = C; jb.N = D_DIM; jb.vmode = 0;
    gemm_body(jb, gsm);
}

// ---------------------------------------------------------------------------
// Fused RMSNorm + RoPE for Q and K in one launch; writes tf32+perm in place.
// ---------------------------------------------------------------------------
#define RMS_QW (NTOK * NH)
#define RMS_TW (NTOK * (NH + NKV))

__global__ __launch_bounds__(256) void rms_rope_all(
    float* __restrict__ Q, float* __restrict__ K,
    const float* __restrict__ gain)
{
    int gw = (blockIdx.x * blockDim.x + threadIdx.x) >> 5;
    int lane = threadIdx.x & 31;
    if (gw >= RMS_TW) return;

    float* p;
    int token;
    float gmul;
    if (gw < RMS_QW) {
        token = gw >> 4;
        int h = gw & 15;
        p = Q + (size_t)token * D_DIM + h * HD;
        gmul = gain[h] * 0.088388347648318447f;
    } else {
        int gw2 = gw - RMS_QW;
        token = gw2 >> 2;
        int h = gw2 & 3;
        p = K + (size_t)token * KVD + h * HD;
        gmul = 1.0f;
    }

    float a1 = p[lane];
    float b1 = p[lane + 32];
    float a2 = p[lane + 64];
    float b2 = p[lane + 96];

    float ss = a1 * a1 + b1 * b1 + a2 * a2 + b2 * b2;
#pragma unroll
    for (int off = 16; off; off >>= 1)
        ss += __shfl_xor_sync(0xffffffffu, ss, off);

    float g = rsqrtf(ss * (1.0f / 128.0f) + EPS_F) * gmul;

    int pos = token & (S_LEN - 1);
    const float c = -0.20762050593046015f;  // -log2(10000)/64
    float invfa = exp2f(c * (float)lane);
    float invfb = exp2f(c * (float)(lane + 32));
    float sa, ca, sb, cb;
    sincosf((float)pos * invfa, &sa, &ca);
    sincosf((float)pos * invfb, &sb, &cb);

    p[perm16(lane)]      = __uint_as_float(f2tf32((a1 * ca + a2 * sa) * g));
    p[perm16(lane + 64)] = __uint_as_float(f2tf32((a2 * ca - a1 * sa) * g));
    p[perm16(lane + 32)] = __uint_as_float(f2tf32((b1 * cb + b2 * sb) * g));
    p[perm16(lane + 96)] = __uint_as_float(f2tf32((b2 * cb - b1 * sb) * g));
}

// ---------------------------------------------------------------------------
// Causal flash attention v6: q-tile 128, 512 threads (16 warps = 8 pairs),
// 1 CTA/SM but 16 warps. Qs in smem (loaded once). Pair pr owns 16 q-rows:
// QK^T key-half split (sacc[4][4]), softmax pair-exchange, PV d-half split.
// Chip mma count and KV traffic identical to R8.
// ---------------------------------------------------------------------------
#define QROWS 132
#define VROWS 68
#define PROWS 68
#define FL_SMEM ((128 * QROWS + 64 * QROWS + 128 * VROWS + 128 * PROWS + 1024) * 4)

__global__ __launch_bounds__(512, 1) void flash_tf32()
{
    extern __shared__ __align__(16) uint32_t usm[];
    uint32_t* Qs = usm;                    // [128][QROWS]
    uint32_t* Ks = Qs + 128 * QROWS;       // [64][QROWS]
    uint32_t* Vt = Ks + 64 * QROWS;        // [128][VROWS]
    uint32_t* Ps = Vt + 128 * VROWS;       // [128][PROWS]  (8 pairs x 16 rows)
    float* Smx = (float*)(Ps + 128 * PROWS);    // [8 pair][2 half][32]
    float* Ssm = Smx + 512;                     // [8 pair][2 half][32]
    const uint32_t Ksu = smem_u32(Ks);
    const uint32_t Vtu = smem_u32(Vt);

    const int qt = gridDim.x - 1 - blockIdx.x;   // LPT
    const int bh = blockIdx.y;
    const int b = bh >> 4, h = bh & 15, kvh = h >> 2;
    const int tid = threadIdx.x;
    const int lane = tid & 31, w = tid >> 5;
    const int pr = w >> 1, half = w & 1;
    const int g = lane >> 2, tg = lane & 3;

    const float* Qg = g_Q + ((size_t)(b * S_LEN + qt * 128)) * D_DIM + h * HD;
    const float* Kg = g_K + ((size_t)b * S_LEN) * KVD + kvh * HD;
    const float* Vg = g_Vt + (size_t)(kvh * HD) * NTOK + b * S_LEN;

    // Loaders: 512 threads, 4 x cp.async(16B) each per tile.
    const int krow = tid >> 3, kq = tid & 7;     // K: [64][128] fl = 32 uint4/row
    const int vd2 = tid >> 2, vq = tid & 3;      // Vt: [128][64] fl = 16 uint4/row
    auto issueK = [&](int kt) {
        const float* src = Kg + (size_t)(kt * 64 + krow) * KVD;
        const uint32_t dst = Ksu + (uint32_t)(krow * QROWS * 4);
#pragma unroll
        for (int i = 0; i < 4; i++) {
            const int u = kq + i * 8;
            CP_ASYNC16(dst + u * 16, src + u * 4);
        }
    };
    auto issueV = [&](int kt) {
        const float* src = Vg + (size_t)vd2 * NTOK + kt * 64;
        const uint32_t dst = Vtu + (uint32_t)(vd2 * VROWS * 4);
#pragma unroll
        for (int i = 0; i < 4; i++) {
            const int u = vq + i * 4;
            CP_ASYNC16(dst + u * 16, src + u * 4);
        }
    };

    const int nkt = 2 * qt + 2;
    issueK(0); CP_COMMIT();
    issueV(0); CP_COMMIT();

    // Q tile copy once (already tf32+permuted): 128 rows x 32 uint4 = 4096
#pragma unroll
    for (int i = 0; i < 8; i++) {
        int idx = tid + i * 512;
        int row = idx >> 5, c4 = idx & 31;
        *(uint4*)&Qs[row * QROWS + c4 * 4] =
            *(const uint4*)(Qg + (size_t)row * D_DIM + c4 * 4);
    }

    float o[8][4];
#pragma unroll
    for (int nt = 0; nt < 8; nt++)
#pragma unroll
        for (int r = 0; r < 4; r++) o[nt][r] = 0.0f;
    float m0 = -1e30f, m1 = -1e30f, l0 = 0.0f, l1 = 0.0f;

    const int ntb = half * 4;
    float* myMx = Smx + (pr * 2 + half) * 32;
    float* otMx = Smx + (pr * 2 + (1 - half)) * 32;
    float* mySm = Ssm + (pr * 2 + half) * 32;
    float* otSm = Ssm + (pr * 2 + (1 - half)) * 32;

    for (int kt = 0; kt < nkt; kt++) {
        const int kn = (kt + 1 < nkt) ? kt + 1 : kt;

        CP_WAIT(1);        // Ks[kt] ready
        __syncthreads();   // also covers Qs init on first iteration

        // S = Q @ K^T for this warp's 32-key half (Q from smem)
        float sacc[4][4];
#pragma unroll
        for (int nt2 = 0; nt2 < 4; nt2++)
#pragma unroll
            for (int r = 0; r < 4; r++) sacc[nt2][r] = 0.0f;

#pragma unroll
        for (int ch = 0; ch < 8; ch++) {
            const uint4 a0 = *(const uint4*)&Qs[(pr * 16 + g) * QROWS + ch * 16 + 4 * tg];
            const uint4 a1 = *(const uint4*)&Qs[(pr * 16 + g + 8) * QROWS + ch * 16 + 4 * tg];
#pragma unroll
            for (int nt2 = 0; nt2 < 4; nt2++) {
                const int nt = ntb + nt2;
                uint4 bf = *(const uint4*)&Ks[(nt * 8 + g) * QROWS + ch * 16 + 4 * tg];
                mma_tf32(sacc[nt2][0], sacc[nt2][1], sacc[nt2][2], sacc[nt2][3],
                         a0.x, a1.x, a0.y, a1.y, bf.x, bf.y);
                mma_tf32(sacc[nt2][0], sacc[nt2][1], sacc[nt2][2], sacc[nt2][3],
                         a0.z, a1.z, a0.w, a1.w, bf.z, bf.w);
            }
        }

        CP_WAIT(0);        // Vt[kt] ready
        __syncthreads();   // all warps done reading Ks[kt]

        issueK(kn); CP_COMMIT();

        if (kt >= 2 * qt) {    // diagonal tiles
            const int q0 = qt * 128 + pr * 16 + g;
            const int q1 = q0 + 8;
#pragma unroll
            for (int nt2 = 0; nt2 < 4; nt2++) {
                int k0 = kt * 64 + (ntb + nt2) * 8 + 2 * tg;
                if (k0 > q0)     sacc[nt2][0] = -1e30f;
                if (k0 + 1 > q0) sacc[nt2][1] = -1e30f;
                if (k0 > q1)     sacc[nt2][2] = -1e30f;
                if (k0 + 1 > q1) sacc[nt2][3] = -1e30f;
            }
        }

        // Half-max over this warp's 32 keys
        float mx0 = -1e30f, mx1 = -1e30f;
#pragma unroll
        for (int nt2 = 0; nt2 < 4; nt2++) {
            mx0 = fmaxf(mx0, fmaxf(sacc[nt2][0], sacc[nt2][1]));
            mx1 = fmaxf(mx1, fmaxf(sacc[nt2][2], sacc[nt2][3]));
        }
        mx0 = fmaxf(mx0, __shfl_xor_sync(0xffffffffu, mx0, 1));
        mx0 = fmaxf(mx0, __shfl_xor_sync(0xffffffffu, mx0, 2));
        mx1 = fmaxf(mx1, __shfl_xor_sync(0xffffffffu, mx1, 1));
        mx1 = fmaxf(mx1, __shfl_xor_sync(0xffffffffu, mx1, 2));

        // Pair exchange #1: half-max -> global row max
        if (tg == 0) { myMx[g] = mx0; myMx[16 + g] = mx1; }
        asm volatile("bar.sync %0, 64;" :: "r"(pr + 1) : "memory");
        const float gmx0 = fmaxf(mx0, otMx[g]);
        const float gmx1 = fmaxf(mx1, otMx[16 + g]);

        const float nm0 = fmaxf(m0, gmx0), nm1 = fmaxf(m1, gmx1);
        const float cr0 = __expf(m0 - nm0), cr1 = __expf(m1 - nm1);
        m0 = nm0; m1 = nm1;

        // exp + P write for this warp's key half
        float s0 = 0.0f, s1 = 0.0f;
#pragma unroll
        for (int nt2 = 0; nt2 < 4; nt2++) {
            const int nt = ntb + nt2;
#pragma unroll
            for (int jj = 0; jj < 2; jj++) {
                int kk = nt * 8 + 2 * tg + jj;
                int kp = perm16(kk);
                float p0 = __expf(sacc[nt2][jj] - nm0);
                s0 += p0;
                Ps[(pr * 16 + g) * PROWS + kp] = f2tf32(p0);
                float p1 = __expf(sacc[nt2][2 + jj] - nm1);
                s1 += p1;
                Ps[(pr * 16 + g + 8) * PROWS + kp] = f2tf32(p1);
            }
        }
        s0 += __shfl_xor_sync(0xffffffffu, s0, 1);
        s0 += __shfl_xor_sync(0xffffffffu, s0, 2);
        s1 += __shfl_xor_sync(0xffffffffu, s1, 1);
        s1 += __shfl_xor_sync(0xffffffffu, s1, 2);
        if (tg == 0) { mySm[g] = s0; mySm[16 + g] = s1; }

        // Pair exchange #2: P halves + partial sums visible
        asm volatile("bar.sync %0, 64;" :: "r"(pr + 1) : "memory");
        l0 = l0 * cr0 + s0 + otSm[g];
        l1 = l1 * cr1 + s1 + otSm[16 + g];

#pragma unroll
        for (int nt = 0; nt < 8; nt++) {
            o[nt][0] *= cr0; o[nt][1] *= cr0;
            o[nt][2] *= cr1; o[nt][3] *= cr1;
        }

        // O += P @ V for this warp's d half (full 64 keys)
#pragma unroll
        for (int ck = 0; ck < 4; ck++) {
            uint4 p0 = *(const uint4*)&Ps[(pr * 16 + g) * PROWS + ck * 16 + 4 * tg];
            uint4 p1 = *(const uint4*)&Ps[(pr * 16 + g + 8) * PROWS + ck * 16 + 4 * tg];
#pragma unroll
            for (int nt = 0; nt < 8; nt++) {
                uint4 bf = *(const uint4*)
                    &Vt[(half * 64 + nt * 8 + g) * VROWS + ck * 16 + 4 * tg];
                mma_tf32(o[nt][0], o[nt][1], o[nt][2], o[nt][3],
                         p0.x, p1.x, p0.y, p1.y, bf.x, bf.y);
                mma_tf32(o[nt][0], o[nt][1], o[nt][2], o[nt][3],
                         p0.z, p1.z, p0.w, p1.w, bf.z, bf.w);
            }
        }

        __syncthreads();           // all Vt/Ps reads done
        issueV(kn); CP_COMMIT();
    }

    const float inv0 = 1.0f / l0, inv1 = 1.0f / l1;
    float* Og = g_AO +
        ((size_t)(b * S_LEN + qt * 128 + pr * 16 + g)) * D_DIM + h * HD;
#pragma unroll
    for (int nt = 0; nt < 8; nt++) {
        const int col = half * 64 + nt * 8 + 2 * tg;
        const int pc0 = perm16(col), pc1 = perm16(col + 1);
        Og[pc0] = __uint_as_float(f2tf32(o[nt][0] * inv0));
        Og[pc1] = __uint_as_float(f2tf32(o[nt][1] * inv0));
        Og[(size_t)8 * D_DIM + pc0] = __uint_as_float(f2tf32(o[nt][2] * inv1));
        Og[(size_t)8 * D_DIM + pc1] = __uint_as_float(f2tf32(o[nt][3] * inv1));
    }
}

// ---------------------------------------------------------------------------
// Launch
// ---------------------------------------------------------------------------
extern "C" void kernel_launch(void* const* d_in, const int* in_sizes, int n_in,
                              void* d_out, int out_size)
{
    const float* x  = (const float*)d_in[0];
    const float* Wq = (const float*)d_in[1];
    const float* bq = (const float*)d_in[2];
    const float* Wk = (const float*)d_in[3];
    const float* bk = (const float*)d_in[4];
    const float* Wv = (const float*)d_in[5];
    const float* bv = (const float*)d_in[6];
    const float* Wo = (const float*)d_in[7];
    const float* bo = (const float*)d_in[8];
    const float* qg = (const float*)d_in[9];
    float* out = (float*)d_out;

    float *Q, *K;
    cudaGetSymbolAddress((void**)&Q, g_Q);
    cudaGetSymbolAddress((void**)&K, g_K);

    const int gemm_smem = 4 * 2048 * 2 * 4;  // 65536
    cudaFuncSetAttribute(gemm_qkv,
                         cudaFuncAttributeMaxDynamicSharedMemorySize, gemm_smem);
    cudaFuncSetAttribute(gemm_out,
                         cudaFuncAttributeMaxDynamicSharedMemorySize, gemm_smem);
    cudaFuncSetAttribute(flash_tf32,
                         cudaFuncAttributeMaxDynamicSharedMemorySize, FL_SMEM);

    // 1. Pre-convert all operands
    convert_all<<<(SEG4 + 255) / 256, 256>>>(x, Wq, Wk, Wv, Wo);

    // 2. Fused Q+K+V projections
    gemm_qkv<<<768, 256, gemm_smem>>>(bq, bk, bv);

    // 3. RMSNorm + RoPE (Q and K in one launch)
    rms_rope_all<<<(RMS_TW / 8), 256>>>(Q, K, qg);

    // 4. Causal flash attention (v6: q-tile 128, 512 thr, pair-split, LPT)
    flash_tf32<<<dim3(S_LEN / 128, B_SZ * NH), 512, FL_SMEM>>>();

    // 5. Output projection
    gemm_out<<<dim3(D_DIM / 128, NTOK / 128), 256, gemm_smem>>>(bo, out);
}

// round 13
// speedup vs baseline: 1.3872x; 1.0807x over previous
#include <cuda_runtime.h>
#include <cstdint>
#include <math.h>

#define S_LEN 2048
#define D_DIM 2048
#define B_SZ  2
#define NH    16
#define NKV   4
#define HD    128
#define NTOK  (B_SZ * S_LEN)   /* 4096 */
#define KVD   (NKV * HD)       /* 512  */
#define EPS_F 1.1920929e-07f

// Scratch (allocation-free rule: __device__ globals)
__device__ float g_Q[(size_t)NTOK * D_DIM];    // tf32+perm after rms_rope
__device__ float g_K[(size_t)NTOK * KVD];
__device__ float g_Vt[(size_t)KVD * NTOK];     // V^T [KVD][NTOK], tok-perm
__device__ float g_AO[(size_t)NTOK * D_DIM];   // tf32+perm (written by flash)
// Pre-converted (tf32-rounded, 16-chunk k-permuted) operands
__device__ float g_xt[(size_t)NTOK * D_DIM];
__device__ float g_Wqt[(size_t)D_DIM * D_DIM];
__device__ float g_Wkt[(size_t)KVD * D_DIM];
__device__ float g_Wvt[(size_t)KVD * D_DIM];
__device__ float g_Wot[(size_t)D_DIM * D_DIM];

__device__ __forceinline__ uint32_t f2tf32(float x) {
    uint32_t r;
    asm("cvt.rna.tf32.f32 %0, %1;" : "=r"(r) : "f"(x));
    return r;
}
__device__ __forceinline__ uint32_t smem_u32(const void* p) {
    uint32_t a;
    asm("{ .reg .u64 t; cvta.to.shared.u64 t, %1; cvt.u32.u64 %0, t; }"
        : "=r"(a) : "l"(p));
    return a;
}
__device__ __forceinline__ int perm16(int c) {
    return (c & ~15) | ((c & 3) << 2) | ((c >> 2) & 3);
}

#define CP_ASYNC16(dst, src) \
    asm volatile("cp.async.cg.shared.global [%0], [%1], 16;" :: "r"(dst), "l"(src))
#define CP_COMMIT() asm volatile("cp.async.commit_group;" ::: "memory")
#define CP_WAIT(n)  asm volatile("cp.async.wait_group %0;" :: "n"(n) : "memory")

// mma.sync m16n8k8 tf32
__device__ __forceinline__ void mma_tf32(
    float& c0, float& c1, float& c2, float& c3,
    uint32_t a0, uint32_t a1, uint32_t a2, uint32_t a3,
    uint32_t b0, uint32_t b1)
{
    asm volatile(
        "mma.sync.aligned.m16n8k8.row.col.f32.tf32.tf32.f32 "
        "{%0,%1,%2,%3}, {%4,%5,%6,%7}, {%8,%9}, {%0,%1,%2,%3};"
        : "+f"(c0), "+f"(c1), "+f"(c2), "+f"(c3)
        : "r"(a0), "r"(a1), "r"(a2), "r"(a3), "r"(b0), "r"(b1));
}

// ---------------------------------------------------------------------------
// Segmented convert: fp32 -> tf32(rna) + 16-chunk k-perm, one launch.
// ---------------------------------------------------------------------------
#define N4_X  (NTOK * D_DIM / 4)
#define N4_WQ (D_DIM * D_DIM / 4)
#define N4_WK (KVD * D_DIM / 4)
#define SEG0 (N4_X)
#define SEG1 (SEG0 + N4_WQ)
#define SEG2 (SEG1 + N4_WK)
#define SEG3 (SEG2 + N4_WK)
#define SEG4 (SEG3 + N4_WQ)

__global__ __launch_bounds__(256) void convert_all(
    const float* __restrict__ x,  const float* __restrict__ Wq,
    const float* __restrict__ Wk, const float* __restrict__ Wv,
    const float* __restrict__ Wo)
{
    int i = blockIdx.x * 256 + threadIdx.x;
    if (i >= SEG4) return;
    const float* src;
    float* dst;
    int j;
    if (i < SEG0)      { src = x;  dst = g_xt;  j = i; }
    else if (i < SEG1) { src = Wq; dst = g_Wqt; j = i - SEG0; }
    else if (i < SEG2) { src = Wk; dst = g_Wkt; j = i - SEG1; }
    else if (i < SEG3) { src = Wv; dst = g_Wvt; j = i - SEG2; }
    else               { src = Wo; dst = g_Wot; j = i - SEG3; }
    float4 v = ((const float4*)src)[j];
    int f0 = j << 2;
    int base = f0 & ~15;
    int q = (f0 >> 2) & 3;
    dst[base + 0 + q]  = __uint_as_float(f2tf32(v.x));
    dst[base + 4 + q]  = __uint_as_float(f2tf32(v.y));
    dst[base + 8 + q]  = __uint_as_float(f2tf32(v.z));
    dst[base + 12 + q] = __uint_as_float(f2tf32(v.w));
}

// ---------------------------------------------------------------------------
// Shared GEMM body: 128x128 tile, 4-stage cp.async, BK=16.
// ---------------------------------------------------------------------------
struct GemmJob {
    const float* Ap;
    const float* Bp;
    const float* bias;
    float* C;
    int N, K, rowBase, colBase, vmode;
};

__device__ __forceinline__ void gemm_body(const GemmJob& jb, float* gsm)
{
    float* sA = gsm;
    float* sB = gsm + 4 * 2048;
    const uint32_t sAu = smem_u32(sA);
    const uint32_t sBu = smem_u32(sB);

    const int tid = threadIdx.x;
    const int lane = tid & 31, wid = tid >> 5;
    const int wm = wid >> 1, wn = wid & 1;
    const int g = lane >> 2, tg = lane & 3;
    const int lrow = tid >> 2;
    const int lc4 = tid & 3;
    const int K = jb.K;

    float acc[2][8][4];
#pragma unroll
    for (int mt = 0; mt < 2; mt++)
#pragma unroll
        for (int nt = 0; nt < 8; nt++)
#pragma unroll
            for (int r = 0; r < 4; r++) acc[mt][nt][r] = 0.0f;

    const int NT = K >> 4;

    auto issue = [&](int slot, int t) {
#pragma unroll
        for (int p = 0; p < 2; p++) {
            const int row = lrow + p * 64;
            const size_t go = (size_t)row * K + t * 16 + lc4 * 4;
            const uint32_t so = (uint32_t)((slot * 2048 + row * 16 + lc4 * 4) * 4);
            CP_ASYNC16(sAu + so, jb.Ap + go);
            CP_ASYNC16(sBu + so, jb.Bp + go);
        }
    };

#pragma unroll
    for (int s = 0; s < 3; s++) { issue(s, s); CP_COMMIT(); }

    for (int t = 0; t < NT; t++) {
        CP_WAIT(2);
        __syncthreads();
        const int tn = t + 3;
        if (tn < NT) issue(tn & 3, tn);
        CP_COMMIT();

        const float* bA = sA + (t & 3) * 2048;
        const float* bB = sB + (t & 3) * 2048;

        uint4 afr[2][2];
#pragma unroll
        for (int mt = 0; mt < 2; mt++) {
            const int r0 = wm * 32 + mt * 16 + g;
            afr[mt][0] = *(const uint4*)&bA[r0 * 16 + 4 * tg];
            afr[mt][1] = *(const uint4*)&bA[(r0 + 8) * 16 + 4 * tg];
        }
        uint4 bfr[8];
#pragma unroll
        for (int nt = 0; nt < 8; nt++)
            bfr[nt] = *(const uint4*)&bB[(wn * 64 + nt * 8 + g) * 16 + 4 * tg];

#pragma unroll
        for (int mt = 0; mt < 2; mt++)
#pragma unroll
            for (int nt = 0; nt < 8; nt++)
                mma_tf32(acc[mt][nt][0], acc[mt][nt][1], acc[mt][nt][2], acc[mt][nt][3],
                         afr[mt][0].x, afr[mt][1].x, afr[mt][0].y, afr[mt][1].y,
                         bfr[nt].x, bfr[nt].y);
#pragma unroll
        for (int mt = 0; mt < 2; mt++)
#pragma unroll
            for (int nt = 0; nt < 8; nt++)
                mma_tf32(acc[mt][nt][0], acc[mt][nt][1], acc[mt][nt][2], acc[mt][nt][3],
                         afr[mt][0].z, afr[mt][1].z, afr[mt][0].w, afr[mt][1].w,
                         bfr[nt].z, bfr[nt].w);
    }

    if (!jb.vmode) {
#pragma unroll
        for (int mt = 0; mt < 2; mt++) {
            const int row = jb.rowBase + wm * 32 + mt * 16 + g;
#pragma unroll
            for (int nt = 0; nt < 8; nt++) {
                const int col = jb.colBase + wn * 64 + nt * 8 + 2 * tg;
                const float2 bb = *(const float2*)(jb.bias + col);
                float2 o0, o1;
                o0.x = acc[mt][nt][0] + bb.x;
                o0.y = acc[mt][nt][1] + bb.y;
                o1.x = acc[mt][nt][2] + bb.x;
                o1.y = acc[mt][nt][3] + bb.y;
                *(float2*)(jb.C + (size_t)row * jb.N + col) = o0;
                *(float2*)(jb.C + (size_t)(row + 8) * jb.N + col) = o1;
            }
        }
    } else {
#pragma unroll
        for (int mt = 0; mt < 2; mt++) {
            const int r = jb.rowBase + wm * 32 + mt * 16 + g;
            const int rp0 = perm16(r);
            const int rp1 = perm16(r + 8);
#pragma unroll
            for (int nt = 0; nt < 8; nt++) {
                const int col = jb.colBase + wn * 64 + nt * 8 + 2 * tg;
                const float b0 = jb.bias[col], b1 = jb.bias[col + 1];
                jb.C[(size_t)col * NTOK + rp0] =
                    __uint_as_float(f2tf32(acc[mt][nt][0] + b0));
                jb.C[(size_t)(col + 1) * NTOK + rp0] =
                    __uint_as_float(f2tf32(acc[mt][nt][1] + b1));
                jb.C[(size_t)col * NTOK + rp1] =
                    __uint_as_float(f2tf32(acc[mt][nt][2] + b0));
                jb.C[(size_t)(col + 1) * NTOK + rp1] =
                    __uint_as_float(f2tf32(acc[mt][nt][3] + b1));
            }
        }
    }
}

// ---------------------------------------------------------------------------
// Fused Q+K+V projection, one launch, flat 768-block grid.
// ---------------------------------------------------------------------------
__global__ __launch_bounds__(256) void gemm_qkv(
    const float* __restrict__ bq, const float* __restrict__ bk,
    const float* __restrict__ bv)
{
    extern __shared__ __align__(16) float gsm[];
    GemmJob jb;
    jb.K = D_DIM;
    const int blk = blockIdx.x;
    if (blk < 512) {
        jb.rowBase = (blk >> 4) * 128; jb.colBase = (blk & 15) * 128;
        jb.Bp = g_Wqt + (size_t)jb.colBase * D_DIM;
        jb.bias = bq; jb.C = g_Q; jb.N = D_DIM; jb.vmode = 0;
    } else if (blk < 640) {
        const int t = blk - 512;
        jb.rowBase = (t >> 2) * 128; jb.colBase = (t & 3) * 128;
        jb.Bp = g_Wkt + (size_t)jb.colBase * D_DIM;
        jb.bias = bk; jb.C = g_K; jb.N = KVD; jb.vmode = 0;
    } else {
        const int t = blk - 640;
        jb.rowBase = (t >> 2) * 128; jb.colBase = (t & 3) * 128;
        jb.Bp = g_Wvt + (size_t)jb.colBase * D_DIM;
        jb.bias = bv; jb.C = g_Vt; jb.N = KVD; jb.vmode = 1;
    }
    jb.Ap = g_xt + (size_t)jb.rowBase * D_DIM;
    gemm_body(jb, gsm);
}

__global__ __launch_bounds__(256) void gemm_out(
    const float* __restrict__ bias, float* __restrict__ C)
{
    extern __shared__ __align__(16) float gsm[];
    GemmJob jb;
    jb.K = D_DIM;
    jb.rowBase = blockIdx.y * 128;
    jb.colBase = blockIdx.x * 128;
    jb.Ap = g_AO + (size_t)jb.rowBase * D_DIM;
    jb.Bp = g_Wot + (size_t)jb.colBase * D_DIM;
    jb.bias = bias; jb.C = C; jb.N = D_DIM; jb.vmode = 0;
    gemm_body(jb, gsm);
}

// ---------------------------------------------------------------------------
// Fused RMSNorm + RoPE for Q and K in one launch; writes tf32+perm in place.
// ---------------------------------------------------------------------------
#define RMS_QW (NTOK * NH)
#define RMS_TW (NTOK * (NH + NKV))

__global__ __launch_bounds__(256) void rms_rope_all(
    float* __restrict__ Q, float* __restrict__ K,
    const float* __restrict__ gain)
{
    int gw = (blockIdx.x * blockDim.x + threadIdx.x) >> 5;
    int lane = threadIdx.x & 31;
    if (gw >= RMS_TW) return;

    float* p;
    int token;
    float gmul;
    if (gw < RMS_QW) {
        token = gw >> 4;
        int h = gw & 15;
        p = Q + (size_t)token * D_DIM + h * HD;
        gmul = gain[h] * 0.088388347648318447f;
    } else {
        int gw2 = gw - RMS_QW;
        token = gw2 >> 2;
        int h = gw2 & 3;
        p = K + (size_t)token * KVD + h * HD;
        gmul = 1.0f;
    }

    float a1 = p[lane];
    float b1 = p[lane + 32];
    float a2 = p[lane + 64];
    float b2 = p[lane + 96];

    float ss = a1 * a1 + b1 * b1 + a2 * a2 + b2 * b2;
#pragma unroll
    for (int off = 16; off; off >>= 1)
        ss += __shfl_xor_sync(0xffffffffu, ss, off);

    float g = rsqrtf(ss * (1.0f / 128.0f) + EPS_F) * gmul;

    int pos = token & (S_LEN - 1);
    const float c = -0.20762050593046015f;  // -log2(10000)/64
    float invfa = exp2f(c * (float)lane);
    float invfb = exp2f(c * (float)(lane + 32));
    float sa, ca, sb, cb;
    sincosf((float)pos * invfa, &sa, &ca);
    sincosf((float)pos * invfb, &sb, &cb);

    p[perm16(lane)]      = __uint_as_float(f2tf32((a1 * ca + a2 * sa) * g));
    p[perm16(lane + 64)] = __uint_as_float(f2tf32((a2 * ca - a1 * sa) * g));
    p[perm16(lane + 32)] = __uint_as_float(f2tf32((b1 * cb + b2 * sb) * g));
    p[perm16(lane + 96)] = __uint_as_float(f2tf32((b2 * cb - b1 * sb) * g));
}

// ---------------------------------------------------------------------------
// Causal flash attention (R8 configuration — best measured):
// q-tile 128, 256 threads (8 warps x 16 q-rows), warp-private P (syncwarp),
// cp.async pipeline (V overlaps QK^T, next K overlaps softmax+PV), LPT.
// ---------------------------------------------------------------------------
#define QROWS 132
#define VROWS 68
#define FL_SMEM ((128 * QROWS + 64 * QROWS + 128 * VROWS + 8 * 16 * VROWS) * 4)

__global__ __launch_bounds__(256) void flash_tf32()
{
    extern __shared__ __align__(16) uint32_t usm[];
    uint32_t* Qs = usm;                    // [128][QROWS]
    uint32_t* Ks = Qs + 128 * QROWS;       // [64][QROWS]
    uint32_t* Vt = Ks + 64 * QROWS;        // [128][VROWS]
    uint32_t* Ps = Vt + 128 * VROWS;       // [8][16][VROWS]
    const uint32_t Ksu = smem_u32(Ks);
    const uint32_t Vtu = smem_u32(Vt);

    const int qt = gridDim.x - 1 - blockIdx.x;   // LPT
    const int bh = blockIdx.y;
    const int b = bh >> 4, h = bh & 15, kvh = h >> 2;
    const int tid = threadIdx.x;
    const int lane = tid & 31, w = tid >> 5;
    const int g = lane >> 2, tg = lane & 3;

    const float* Qg = g_Q + ((size_t)(b * S_LEN + qt * 128)) * D_DIM + h * HD;
    const float* Kg = g_K + ((size_t)b * S_LEN) * KVD + kvh * HD;
    const float* Vg = g_Vt + (size_t)(kvh * HD) * NTOK + b * S_LEN;

    const int krow = tid >> 5, kc4 = tid & 31;
    const int vd = tid >> 4, vc4 = tid & 15;
    auto issueK = [&](int kt) {
#pragma unroll
        for (int i = 0; i < 8; i++) {
            int row = krow + i * 8;
            CP_ASYNC16(Ksu + (uint32_t)((row * QROWS + kc4 * 4) * 4),
                       Kg + (size_t)(kt * 64 + row) * KVD + kc4 * 4);
        }
    };
    auto issueV = [&](int kt) {
#pragma unroll
        for (int i = 0; i < 8; i++) {
            int d = vd + i * 16;
            CP_ASYNC16(Vtu + (uint32_t)((d * VROWS + vc4 * 4) * 4),
                       Vg + (size_t)d * NTOK + kt * 64 + vc4 * 4);
        }
    };

    const int nkt = 2 * qt + 2;
    issueK(0); CP_COMMIT();
    issueV(0); CP_COMMIT();

#pragma unroll
    for (int i = 0; i < 16; i++) {
        int idx = tid + i * 256;
        int row = idx >> 5, c4 = idx & 31;
        *(uint4*)&Qs[row * QROWS + c4 * 4] =
            *(const uint4*)(Qg + (size_t)row * D_DIM + c4 * 4);
    }

    float o[16][4];
#pragma unroll
    for (int nt = 0; nt < 16; nt++)
#pragma unroll
        for (int r = 0; r < 4; r++) o[nt][r] = 0.0f;
    float m0 = -1e30f, m1 = -1e30f, l0 = 0.0f, l1 = 0.0f;

    uint32_t* Pw = Ps + w * 16 * VROWS;

    for (int kt = 0; kt < nkt; kt++) {
        const int kn = (kt + 1 < nkt) ? kt + 1 : kt;

        CP_WAIT(1);
        __syncthreads();

        float sacc[8][4];
#pragma unroll
        for (int nt = 0; nt < 8; nt++)
#pragma unroll
            for (int r = 0; r < 4; r++) sacc[nt][r] = 0.0f;

#pragma unroll
        for (int ch = 0; ch < 8; ch++) {
            uint4 a0 = *(const uint4*)&Qs[(w * 16 + g) * QROWS + ch * 16 + 4 * tg];
            uint4 a1 = *(const uint4*)&Qs[(w * 16 + g + 8) * QROWS + ch * 16 + 4 * tg];
#pragma unroll
            for (int nt = 0; nt < 8; nt++) {
                uint4 bf = *(const uint4*)&Ks[(nt * 8 + g) * QROWS + ch * 16 + 4 * tg];
                mma_tf32(sacc[nt][0], sacc[nt][1], sacc[nt][2], sacc[nt][3],
                         a0.x, a1.x, a0.y, a1.y, bf.x, bf.y);
                mma_tf32(sacc[nt][0], sacc[nt][1], sacc[nt][2], sacc[nt][3],
                         a0.z, a1.z, a0.w, a1.w, bf.z, bf.w);
            }
        }

        CP_WAIT(0);
        __syncthreads();

        issueK(kn); CP_COMMIT();

        if (kt >= 2 * qt) {
            const int q0 = qt * 128 + w * 16 + g;
            const int q1 = q0 + 8;
#pragma unroll
            for (int nt = 0; nt < 8; nt++) {
                int k0 = kt * 64 + nt * 8 + 2 * tg;
                if (k0 > q0)     sacc[nt][0] = -1e30f;
                if (k0 + 1 > q0) sacc[nt][1] = -1e30f;
                if (k0 > q1)     sacc[nt][2] = -1e30f;
                if (k0 + 1 > q1) sacc[nt][3] = -1e30f;
            }
        }

        float mx0 = -1e30f, mx1 = -1e30f;
#pragma unroll
        for (int nt = 0; nt < 8; nt++) {
            mx0 = fmaxf(mx0, fmaxf(sacc[nt][0], sacc[nt][1]));
            mx1 = fmaxf(mx1, fmaxf(sacc[nt][2], sacc[nt][3]));
        }
        mx0 = fmaxf(mx0, __shfl_xor_sync(0xffffffffu, mx0, 1));
        mx0 = fmaxf(mx0, __shfl_xor_sync(0xffffffffu, mx0, 2));
        mx1 = fmaxf(mx1, __shfl_xor_sync(0xffffffffu, mx1, 1));
        mx1 = fmaxf(mx1, __shfl_xor_sync(0xffffffffu, mx1, 2));
        const float nm0 = fmaxf(m0, mx0), nm1 = fmaxf(m1, mx1);
        const float cr0 = __expf(m0 - nm0), cr1 = __expf(m1 - nm1);
        m0 = nm0; m1 = nm1;

        float s0 = 0.0f, s1 = 0.0f;
#pragma unroll
        for (int nt = 0; nt < 8; nt++) {
#pragma unroll
            for (int jj = 0; jj < 2; jj++) {
                int kk = nt * 8 + 2 * tg + jj;
                int kp = perm16(kk);
                float p0 = __expf(sacc[nt][jj] - nm0);
                s0 += p0;
                Pw[g * VROWS + kp] = f2tf32(p0);
                float p1 = __expf(sacc[nt][2 + jj] - nm1);
                s1 += p1;
                Pw[(g + 8) * VROWS + kp] = f2tf32(p1);
            }
        }
        s0 += __shfl_xor_sync(0xffffffffu, s0, 1);
        s0 += __shfl_xor_sync(0xffffffffu, s0, 2);
        s1 += __shfl_xor_sync(0xffffffffu, s1, 1);
        s1 += __shfl_xor_sync(0xffffffffu, s1, 2);
        l0 = l0 * cr0 + s0;
        l1 = l1 * cr1 + s1;

#pragma unroll
        for (int nt = 0; nt < 16; nt++) {
            o[nt][0] *= cr0; o[nt][1] *= cr0;
            o[nt][2] *= cr1; o[nt][3] *= cr1;
        }
        __syncwarp();

#pragma unroll
        for (int ck = 0; ck < 4; ck++) {
            uint4 p0 = *(const uint4*)&Pw[g * VROWS + ck * 16 + 4 * tg];
            uint4 p1 = *(const uint4*)&Pw[(g + 8) * VROWS + ck * 16 + 4 * tg];
#pragma unroll
            for (int nt = 0; nt < 16; nt++) {
                uint4 bf = *(const uint4*)&Vt[(nt * 8 + g) * VROWS + ck * 16 + 4 * tg];
                mma_tf32(o[nt][0], o[nt][1], o[nt][2], o[nt][3],
                         p0.x, p1.x, p0.y, p1.y, bf.x, bf.y);
                mma_tf32(o[nt][0], o[nt][1], o[nt][2], o[nt][3],
                         p0.z, p1.z, p0.w, p1.w, bf.z, bf.w);
            }
        }

        __syncthreads();
        issueV(kn); CP_COMMIT();
    }

    const float inv0 = 1.0f / l0, inv1 = 1.0f / l1;
    float* Og = g_AO + ((size_t)(b * S_LEN + qt * 128 + w * 16)) * D_DIM + h * HD;
#pragma unroll
    for (int nt = 0; nt < 16; nt++) {
        const int col = nt * 8 + 2 * tg;
        const int pc0 = perm16(col), pc1 = perm16(col + 1);
        Og[(size_t)g * D_DIM + pc0] = __uint_as_float(f2tf32(o[nt][0] * inv0));
        Og[(size_t)g * D_DIM + pc1] = __uint_as_float(f2tf32(o[nt][1] * inv0));
        Og[(size_t)(g + 8) * D_DIM + pc0] = __uint_as_float(f2tf32(o[nt][2] * inv1));
        Og[(size_t)(g + 8) * D_DIM + pc1] = __uint_as_float(f2tf32(o[nt][3] * inv1));
    }
}

// ---------------------------------------------------------------------------
// Launch
// ---------------------------------------------------------------------------
extern "C" void kernel_launch(void* const* d_in, const int* in_sizes, int n_in,
                              void* d_out, int out_size)
{
    const float* x  = (const float*)d_in[0];
    const float* Wq = (const float*)d_in[1];
    const float* bq = (const float*)d_in[2];
    const float* Wk = (const float*)d_in[3];
    const float* bk = (const float*)d_in[4];
    const float* Wv = (const float*)d_in[5];
    const float* bv = (const float*)d_in[6];
    const float* Wo = (const float*)d_in[7];
    const float* bo = (const float*)d_in[8];
    const float* qg = (const float*)d_in[9];
    float* out = (float*)d_out;

    float *Q, *K;
    cudaGetSymbolAddress((void**)&Q, g_Q);
    cudaGetSymbolAddress((void**)&K, g_K);

    const int gemm_smem = 4 * 2048 * 2 * 4;  // 65536
    cudaFuncSetAttribute(gemm_qkv,
                         cudaFuncAttributeMaxDynamicSharedMemorySize, gemm_smem);
    cudaFuncSetAttribute(gemm_out,
                         cudaFuncAttributeMaxDynamicSharedMemorySize, gemm_smem);
    cudaFuncSetAttribute(flash_tf32,
                         cudaFuncAttributeMaxDynamicSharedMemorySize, FL_SMEM);

    // 1. Pre-convert all operands
    convert_all<<<(SEG4 + 255) / 256, 256>>>(x, Wq, Wk, Wv, Wo);

    // 2. Fused Q+K+V projections
    gemm_qkv<<<768, 256, gemm_smem>>>(bq, bk, bv);

    // 3. RMSNorm + RoPE (Q and K in one launch)
    rms_rope_all<<<(RMS_TW / 8), 256>>>(Q, K, qg);

    // 4. Causal flash attention (R8 config: q-tile 128, 256 thr, LPT)
    flash_tf32<<<dim3(S_LEN / 128, B_SZ * NH), 256, FL_SMEM>>>();

    // 5. Output projection
    gemm_out<<<dim3(D_DIM / 128, NTOK / 128), 256, gemm_smem>>>(bo, out);
}